// round 1
// baseline (speedup 1.0000x reference)
#include <cuda_runtime.h>
#include <cmath>

#define B_  2
#define T_  2048
#define C_  1024
#define H_  16
#define HD_ 64
#define M_  (B_ * T_)     // 4096 rows
#define FF_ (4 * C_)      // 4096

// ---------------- scratch (static device allocations; allowed) ----------------
__device__ float g_Wqkv[C_ * 3 * C_];          // packed [C, 3C] qkv weight
__device__ float g_q[B_ * H_ * T_ * HD_];      // [b,h,t,d]
__device__ float g_k[B_ * H_ * T_ * HD_];
__device__ float g_v[B_ * H_ * T_ * HD_];
__device__ float g_attn[M_ * C_];              // attention out, concat layout [b*t, h*64+d]
__device__ float g_h1[M_ * C_];                // x + attn_proj
__device__ float g_x1[M_ * C_];                // LN1 out
__device__ float g_ff[M_ * FF_];               // relu(x1 W1 + b1)
__device__ float g_h2[M_ * C_];                // x1 + ffn out

// ---------------- weight pack: Wqkv[c][s*1024 + h*64 + d] = Ws[h][c][d] -------
__global__ void pack_qkv_kernel(const float* __restrict__ Wq,
                                const float* __restrict__ Wk,
                                const float* __restrict__ Wv) {
    int idx = blockIdx.x * blockDim.x + threadIdx.x;
    if (idx >= C_ * 3 * C_) return;
    int c   = idx / (3 * C_);
    int rem = idx - c * (3 * C_);
    int s   = rem >> 10;        // 0=q,1=k,2=v
    int r2  = rem & 1023;
    int h   = r2 >> 6;
    int d   = r2 & 63;
    const float* W = (s == 0) ? Wq : ((s == 1) ? Wk : Wv);
    g_Wqkv[idx] = W[(h * C_ + c) * HD_ + d];
}

// ---------------- generic 128x128x16 fp32 GEMM, 256 thr, 8x8/thread ----------
constexpr int EPI_QKV       = 0;  // scatter to g_q/g_k/g_v as [b,h,t,d]
constexpr int EPI_BIAS_RELU = 1;  // C = relu(acc + bias)
constexpr int EPI_BIAS_RES  = 2;  // C = acc + bias + res

template <int EPI>
__global__ __launch_bounds__(256)
void gemm_kernel(const float* __restrict__ A, const float* __restrict__ Bm,
                 const float* __restrict__ bias, const float* __restrict__ res,
                 float* __restrict__ Cout, int M, int N, int K) {
    __shared__ __align__(16) float As[16][128];   // [k][m] (A stored transposed)
    __shared__ __align__(16) float Bs[16][128];   // [k][n]

    const int tid = threadIdx.x;
    const int bm = blockIdx.y * 128;
    const int bn = blockIdx.x * 128;
    const int ty = tid >> 4;      // 0..15
    const int tx = tid & 15;      // 0..15

    float acc[8][8];
#pragma unroll
    for (int i = 0; i < 8; i++)
#pragma unroll
        for (int j = 0; j < 8; j++) acc[i][j] = 0.f;

    for (int k0 = 0; k0 < K; k0 += 16) {
        // A tile: 128 rows x 16 cols = 512 float4
#pragma unroll
        for (int i = tid; i < 512; i += 256) {
            int r  = i >> 2;
            int c4 = (i & 3) << 2;
            float4 av = *(const float4*)(A + (size_t)(bm + r) * K + k0 + c4);
            As[c4 + 0][r] = av.x;
            As[c4 + 1][r] = av.y;
            As[c4 + 2][r] = av.z;
            As[c4 + 3][r] = av.w;
        }
        // B tile: 16 rows x 128 cols = 512 float4
#pragma unroll
        for (int i = tid; i < 512; i += 256) {
            int r  = i >> 5;
            int c4 = (i & 31) << 2;
            *(float4*)&Bs[r][c4] = *(const float4*)(Bm + (size_t)(k0 + r) * N + bn + c4);
        }
        __syncthreads();

#pragma unroll
        for (int kk = 0; kk < 16; kk++) {
            float a[8], b[8];
            *(float4*)(a + 0) = *(const float4*)&As[kk][ty * 8];
            *(float4*)(a + 4) = *(const float4*)&As[kk][ty * 8 + 4];
            *(float4*)(b + 0) = *(const float4*)&Bs[kk][tx * 8];
            *(float4*)(b + 4) = *(const float4*)&Bs[kk][tx * 8 + 4];
#pragma unroll
            for (int i = 0; i < 8; i++)
#pragma unroll
                for (int j = 0; j < 8; j++) acc[i][j] += a[i] * b[j];
        }
        __syncthreads();
    }

#pragma unroll
    for (int i = 0; i < 8; i++) {
        int row = bm + ty * 8 + i;
#pragma unroll
        for (int j = 0; j < 8; j++) {
            int col = bn + tx * 8 + j;
            float v = acc[i][j];
            if (EPI == EPI_QKV) {
                int s  = col >> 10;
                int r2 = col & 1023;
                int h  = r2 >> 6;
                int d  = r2 & 63;
                int b  = row >> 11;     // row = b*T + t
                int t  = row & 2047;
                float* dst = (s == 0) ? g_q : ((s == 1) ? g_k : g_v);
                dst[(((size_t)(b * H_ + h) * T_) + t) * HD_ + d] = v;
            } else if (EPI == EPI_BIAS_RELU) {
                v += bias[col];
                Cout[(size_t)row * N + col] = fmaxf(v, 0.f);
            } else {
                Cout[(size_t)row * N + col] = v + bias[col] + res[(size_t)row * N + col];
            }
        }
    }
}

// ---------------- causal flash attention, fp32 ----------------
// grid: (T/64, B*H).  Each CTA: 64 query rows, loop key blocks of 32.
__global__ __launch_bounds__(256)
void attn_kernel() {
    __shared__ __align__(16) float Qs[64][64];   // [d][r] transposed, pre-scaled
    __shared__ __align__(16) float Ks[64][32];   // [d][c] transposed
    __shared__ __align__(16) float Vs[32][64];   // [c][d]
    __shared__ float Ss[64][33];                 // scores / probs (padded)
    __shared__ float row_alpha[64];
    __shared__ float row_l[64];

    const int tid = threadIdx.x;
    const int bh  = blockIdx.y;          // b*H + h
    const int qr0 = blockIdx.x * 64;
    const float* qb = g_q + (size_t)bh * T_ * HD_;
    const float* kb = g_k + (size_t)bh * T_ * HD_;
    const float* vb = g_v + (size_t)bh * T_ * HD_;

    // load Q tile transposed, pre-scaled by hd^-0.5 = 0.125
    for (int i = tid; i < 1024; i += 256) {
        int r  = i >> 4;
        int d4 = (i & 15) << 2;
        float4 qv = *(const float4*)(qb + (size_t)(qr0 + r) * HD_ + d4);
        Qs[d4 + 0][r] = qv.x * 0.125f;
        Qs[d4 + 1][r] = qv.y * 0.125f;
        Qs[d4 + 2][r] = qv.z * 0.125f;
        Qs[d4 + 3][r] = qv.w * 0.125f;
    }

    const int ty = tid >> 3;     // 0..31
    const int tx = tid & 7;      // 0..7
    const int r0 = ty * 2;       // rows r0, r0+1

    float oacc[2][8];
#pragma unroll
    for (int i = 0; i < 2; i++)
#pragma unroll
        for (int j = 0; j < 8; j++) oacc[i][j] = 0.f;
    float m_reg = -1e30f, l_reg = 0.f;

    for (int kc0 = 0; kc0 <= qr0 + 32; kc0 += 32) {
        __syncthreads();   // prior O-update done (and Q tile ready on iter 0)

        // load K tile transposed and V tile natural: 32 keys x 64 d
        for (int i = tid; i < 512; i += 256) {
            int c  = i >> 4;
            int d4 = (i & 15) << 2;
            float4 kv = *(const float4*)(kb + (size_t)(kc0 + c) * HD_ + d4);
            Ks[d4 + 0][c] = kv.x;
            Ks[d4 + 1][c] = kv.y;
            Ks[d4 + 2][c] = kv.z;
            Ks[d4 + 3][c] = kv.w;
            *(float4*)&Vs[c][d4] = *(const float4*)(vb + (size_t)(kc0 + c) * HD_ + d4);
        }
        __syncthreads();

        // S = Q K^T (64x32), each thread 2x4
        float sacc[2][4];
#pragma unroll
        for (int i = 0; i < 2; i++)
#pragma unroll
            for (int j = 0; j < 4; j++) sacc[i][j] = 0.f;
#pragma unroll
        for (int d = 0; d < 64; d++) {
            float q0 = Qs[d][r0];
            float q1 = Qs[d][r0 + 1];
            float4 kv = *(const float4*)&Ks[d][tx * 4];
            sacc[0][0] += q0 * kv.x; sacc[0][1] += q0 * kv.y;
            sacc[0][2] += q0 * kv.z; sacc[0][3] += q0 * kv.w;
            sacc[1][0] += q1 * kv.x; sacc[1][1] += q1 * kv.y;
            sacc[1][2] += q1 * kv.z; sacc[1][3] += q1 * kv.w;
        }
        bool need_mask = (kc0 + 31 > qr0);
#pragma unroll
        for (int i = 0; i < 2; i++) {
            int rg = qr0 + r0 + i;
#pragma unroll
            for (int j = 0; j < 4; j++) {
                int cg = kc0 + tx * 4 + j;
                float sv = sacc[i][j];
                if (need_mask && cg > rg) sv = -1e30f;
                Ss[r0 + i][tx * 4 + j] = sv;
            }
        }
        __syncthreads();

        // online softmax (thread tid owns row tid for tid<64)
        if (tid < 64) {
            float mx = m_reg;
#pragma unroll
            for (int c = 0; c < 32; c++) mx = fmaxf(mx, Ss[tid][c]);
            float alpha = __expf(m_reg - mx);
            float sum = 0.f;
#pragma unroll
            for (int c = 0; c < 32; c++) {
                float p = __expf(Ss[tid][c] - mx);
                Ss[tid][c] = p;
                sum += p;
            }
            m_reg = mx;
            l_reg = l_reg * alpha + sum;
            row_alpha[tid] = alpha;
        }
        __syncthreads();

        // O = O*alpha + P V, each thread 2x8
        float a0 = row_alpha[r0];
        float a1 = row_alpha[r0 + 1];
#pragma unroll
        for (int j = 0; j < 8; j++) { oacc[0][j] *= a0; oacc[1][j] *= a1; }
#pragma unroll
        for (int c = 0; c < 32; c++) {
            float p0 = Ss[r0][c];
            float p1 = Ss[r0 + 1][c];
            float4 v0 = *(const float4*)&Vs[c][tx * 8];
            float4 v1 = *(const float4*)&Vs[c][tx * 8 + 4];
            oacc[0][0] += p0 * v0.x; oacc[0][1] += p0 * v0.y;
            oacc[0][2] += p0 * v0.z; oacc[0][3] += p0 * v0.w;
            oacc[0][4] += p0 * v1.x; oacc[0][5] += p0 * v1.y;
            oacc[0][6] += p0 * v1.z; oacc[0][7] += p0 * v1.w;
            oacc[1][0] += p1 * v0.x; oacc[1][1] += p1 * v0.y;
            oacc[1][2] += p1 * v0.z; oacc[1][3] += p1 * v0.w;
            oacc[1][4] += p1 * v1.x; oacc[1][5] += p1 * v1.y;
            oacc[1][6] += p1 * v1.z; oacc[1][7] += p1 * v1.w;
        }
    }

    if (tid < 64) row_l[tid] = l_reg;
    __syncthreads();

    const int b = bh >> 4;
    const int h = bh & 15;
#pragma unroll
    for (int i = 0; i < 2; i++) {
        int t = qr0 + r0 + i;
        float inv = 1.f / row_l[r0 + i];
        float* dst = g_attn + ((size_t)(b * T_ + t)) * C_ + h * HD_ + tx * 8;
        float4 o0 = make_float4(oacc[i][0] * inv, oacc[i][1] * inv,
                                oacc[i][2] * inv, oacc[i][3] * inv);
        float4 o1 = make_float4(oacc[i][4] * inv, oacc[i][5] * inv,
                                oacc[i][6] * inv, oacc[i][7] * inv);
        *(float4*)dst       = o0;
        *(float4*)(dst + 4) = o1;
    }
}

// ---------------- LayerNorm over C=1024, 1 row per block ----------------
__global__ __launch_bounds__(256)
void ln_kernel(const float* __restrict__ x, const float* __restrict__ g,
               const float* __restrict__ beta, float* __restrict__ y) {
    const int row = blockIdx.x;
    const int tid = threadIdx.x;
    const float* xr = x + (size_t)row * C_;

    float4 v = *(const float4*)(xr + tid * 4);
    float s  = v.x + v.y + v.z + v.w;
    float s2 = v.x * v.x + v.y * v.y + v.z * v.z + v.w * v.w;
#pragma unroll
    for (int o = 16; o > 0; o >>= 1) {
        s  += __shfl_xor_sync(0xFFFFFFFFu, s, o);
        s2 += __shfl_xor_sync(0xFFFFFFFFu, s2, o);
    }
    __shared__ float sh[16];
    __shared__ float mean_sh, istd_sh;
    int w = tid >> 5, l = tid & 31;
    if (l == 0) { sh[w] = s; sh[w + 8] = s2; }
    __syncthreads();
    if (tid == 0) {
        float ts = 0.f, ts2 = 0.f;
#pragma unroll
        for (int i = 0; i < 8; i++) { ts += sh[i]; ts2 += sh[i + 8]; }
        float mean = ts * (1.f / C_);
        float var  = ts2 * (1.f / C_) - mean * mean;
        mean_sh = mean;
        istd_sh = rsqrtf(var + 1e-5f);
    }
    __syncthreads();
    float mean = mean_sh, istd = istd_sh;
    float4 gv = *(const float4*)(g + tid * 4);
    float4 bv = *(const float4*)(beta + tid * 4);
    float4 out;
    out.x = (v.x - mean) * istd * gv.x + bv.x;
    out.y = (v.y - mean) * istd * gv.y + bv.y;
    out.z = (v.z - mean) * istd * gv.z + bv.z;
    out.w = (v.w - mean) * istd * gv.w + bv.w;
    *(float4*)(y + (size_t)row * C_ + tid * 4) = out;
}

// ---------------- launch ----------------
extern "C" void kernel_launch(void* const* d_in, const int* in_sizes, int n_in,
                              void* d_out, int out_size) {
    (void)in_sizes; (void)n_in; (void)out_size;
    const float* x   = (const float*)d_in[0];
    const float* Wq  = (const float*)d_in[1];
    const float* Wk  = (const float*)d_in[2];
    const float* Wv  = (const float*)d_in[3];
    const float* Wp  = (const float*)d_in[4];
    const float* bp  = (const float*)d_in[5];
    const float* W1  = (const float*)d_in[6];
    const float* b1  = (const float*)d_in[7];
    const float* W2  = (const float*)d_in[8];
    const float* b2  = (const float*)d_in[9];
    const float* g1  = (const float*)d_in[10];
    const float* be1 = (const float*)d_in[11];
    const float* g2  = (const float*)d_in[12];
    const float* be2 = (const float*)d_in[13];

    void *p_wqkv_, *p_attn_, *p_h1_, *p_x1_, *p_ff_, *p_h2_;
    cudaGetSymbolAddress(&p_wqkv_, g_Wqkv);
    cudaGetSymbolAddress(&p_attn_, g_attn);
    cudaGetSymbolAddress(&p_h1_,   g_h1);
    cudaGetSymbolAddress(&p_x1_,   g_x1);
    cudaGetSymbolAddress(&p_ff_,   g_ff);
    cudaGetSymbolAddress(&p_h2_,   g_h2);
    float* p_wqkv = (float*)p_wqkv_;
    float* p_attn = (float*)p_attn_;
    float* p_h1   = (float*)p_h1_;
    float* p_x1   = (float*)p_x1_;
    float* p_ff   = (float*)p_ff_;
    float* p_h2   = (float*)p_h2_;

    // 1. pack qkv weights -> [C, 3C]
    pack_qkv_kernel<<<(C_ * 3 * C_ + 255) / 256, 256>>>(Wq, Wk, Wv);
    // 2. QKV projection: [4096,1024] x [1024,3072], scatter to q/k/v
    gemm_kernel<EPI_QKV><<<dim3(3 * C_ / 128, M_ / 128), 256>>>(
        x, p_wqkv, nullptr, nullptr, nullptr, M_, 3 * C_, C_);
    // 3. causal attention -> concat layout
    attn_kernel<<<dim3(T_ / 64, B_ * H_), 256>>>();
    // 4. out proj + bias + residual
    gemm_kernel<EPI_BIAS_RES><<<dim3(C_ / 128, M_ / 128), 256>>>(
        p_attn, Wp, bp, x, p_h1, M_, C_, C_);
    // 5. LN1
    ln_kernel<<<M_, 256>>>(p_h1, g1, be1, p_x1);
    // 6. FFN up + relu
    gemm_kernel<EPI_BIAS_RELU><<<dim3(FF_ / 128, M_ / 128), 256>>>(
        p_x1, W1, b1, nullptr, p_ff, M_, FF_, C_);
    // 7. FFN down + bias + residual
    gemm_kernel<EPI_BIAS_RES><<<dim3(C_ / 128, M_ / 128), 256>>>(
        p_ff, W2, b2, p_x1, p_h2, M_, C_, FF_);
    // 8. LN2 -> d_out
    ln_kernel<<<M_, 256>>>(p_h2, g2, be2, (float*)d_out);
}

// round 3
// speedup vs baseline: 1.7499x; 1.7499x over previous
#include <cuda_runtime.h>
#include <cstdint>
#include <cmath>

#define B_  2
#define T_  2048
#define C_  1024
#define H_  16
#define HD_ 64
#define M_  (B_ * T_)     // 4096 rows
#define FF_ (4 * C_)      // 4096

// ---------------- scratch (static device allocations; allowed) ----------------
__device__ float g_Wqkv[C_ * 3 * C_];          // packed [C, 3C] qkv weight
__device__ float g_q[B_ * H_ * T_ * HD_];      // [b,h,t,d]
__device__ float g_k[B_ * H_ * T_ * HD_];
__device__ float g_v[B_ * H_ * T_ * HD_];
__device__ float g_attn[M_ * C_];              // attention out, concat layout
__device__ float g_h1[M_ * C_];                // x + attn_proj
__device__ float g_x1[M_ * C_];                // LN1 out
__device__ float g_ff[M_ * FF_];               // relu(x1 W1 + b1)
__device__ float g_h2[M_ * C_];                // x1 + ffn out

// ---------------- tf32 helpers ----------------
__device__ __forceinline__ uint32_t f2tf32(float f) {
    uint32_t r;
    asm("cvt.rna.tf32.f32 %0, %1;" : "=r"(r) : "f"(f));
    return r;
}

// m16n8k8 tf32 MMA (arch-generic, sm_80+; assembles at target sm_100)
__device__ __forceinline__ void mma_tf32(float* d, const uint32_t* a, const uint32_t* b) {
    asm volatile(
        "mma.sync.aligned.m16n8k8.row.col.f32.tf32.tf32.f32 "
        "{%0,%1,%2,%3}, {%4,%5,%6,%7}, {%8,%9}, {%0,%1,%2,%3};\n"
        : "+f"(d[0]), "+f"(d[1]), "+f"(d[2]), "+f"(d[3])
        : "r"(a[0]), "r"(a[1]), "r"(a[2]), "r"(a[3]),
          "r"(b[0]), "r"(b[1]));
}

// ---------------- weight pack ----------------
__global__ void pack_qkv_kernel(const float* __restrict__ Wq,
                                const float* __restrict__ Wk,
                                const float* __restrict__ Wv) {
    int idx = blockIdx.x * blockDim.x + threadIdx.x;
    if (idx >= C_ * 3 * C_) return;
    int c   = idx / (3 * C_);
    int rem = idx - c * (3 * C_);
    int s   = rem >> 10;
    int r2  = rem & 1023;
    int h   = r2 >> 6;
    int d   = r2 & 63;
    const float* W = (s == 0) ? Wq : ((s == 1) ? Wk : Wv);
    g_Wqkv[idx] = W[(h * C_ + c) * HD_ + d];
}

// ============ tf32 mma.sync GEMM: 128x128 CTA tile, BK=32, 8 warps ============
constexpr int EPI_QKV       = 0;
constexpr int EPI_BIAS_RELU = 1;
constexpr int EPI_BIAS_RES  = 2;

#define BM 128
#define BN 128
#define BK 32
#define AS_STRIDE 36    // bank( (4m+k) & 31 ) unique per warp for frag loads
#define BS_STRIDE 136   // bank( (8k+n) & 31 ) unique per warp for frag loads

template <int EPI>
__global__ __launch_bounds__(256, 1)
void gemm_tc(const float* __restrict__ A, const float* __restrict__ Bmat,
             const float* __restrict__ bias, const float* __restrict__ res,
             float* __restrict__ Cout, int M, int N, int K) {
    __shared__ __align__(16) uint32_t As[BM][AS_STRIDE];   // [m][k] tf32 bits
    __shared__ __align__(16) uint32_t Bs[BK][BS_STRIDE];   // [k][n] tf32 bits

    const int tid = threadIdx.x;
    const int wid = tid >> 5;
    const int lane = tid & 31;
    const int g  = lane >> 2;     // group id 0..7
    const int tg = lane & 3;      // thread-in-group 0..3
    const int wm = (wid >> 2) * 64;   // warp m offset: 0 or 64
    const int wn = (wid & 3) * 32;    // warp n offset: 0,32,64,96
    const int bm = blockIdx.y * BM;
    const int bn = blockIdx.x * BN;

    float acc[4][4][4];
#pragma unroll
    for (int mi = 0; mi < 4; mi++)
#pragma unroll
        for (int ni = 0; ni < 4; ni++)
#pragma unroll
            for (int j = 0; j < 4; j++) acc[mi][ni][j] = 0.f;

    const int KT = K / BK;

    float4 aR[4], bR[4];
    {
        const float* Ag = A + (size_t)bm * K;
        const float* Bg = Bmat + bn;
#pragma unroll
        for (int i = 0; i < 4; i++) {
            int f = i * 256 + tid;
            int r = f >> 3, c = f & 7;
            aR[i] = *(const float4*)(Ag + (size_t)r * K + c * 4);
            int k = f >> 5, n4 = f & 31;
            bR[i] = *(const float4*)(Bg + (size_t)k * N + n4 * 4);
        }
    }

    for (int kt = 0; kt < KT; ++kt) {
        // store staged tile to SMEM (convert to tf32 with round-to-nearest)
#pragma unroll
        for (int i = 0; i < 4; i++) {
            int f = i * 256 + tid;
            int r = f >> 3, c = f & 7;
            uint4 t;
            t.x = f2tf32(aR[i].x); t.y = f2tf32(aR[i].y);
            t.z = f2tf32(aR[i].z); t.w = f2tf32(aR[i].w);
            *(uint4*)&As[r][c * 4] = t;
            int k = f >> 5, n4 = f & 31;
            uint4 u;
            u.x = f2tf32(bR[i].x); u.y = f2tf32(bR[i].y);
            u.z = f2tf32(bR[i].z); u.w = f2tf32(bR[i].w);
            *(uint4*)&Bs[k][n4 * 4] = u;
        }
        __syncthreads();

        // issue next tile's global loads early (latency hidden by MMA work)
        if (kt + 1 < KT) {
            const int k0 = (kt + 1) * BK;
            const float* Ag = A + (size_t)bm * K + k0;
            const float* Bg = Bmat + (size_t)k0 * N + bn;
#pragma unroll
            for (int i = 0; i < 4; i++) {
                int f = i * 256 + tid;
                int r = f >> 3, c = f & 7;
                aR[i] = *(const float4*)(Ag + (size_t)r * K + c * 4);
                int k = f >> 5, n4 = f & 31;
                bR[i] = *(const float4*)(Bg + (size_t)k * N + n4 * 4);
            }
        }

        // compute: 4 k-steps of 8
#pragma unroll
        for (int kk8 = 0; kk8 < 4; kk8++) {
            const int kk = kk8 * 8;
            uint32_t af[4][4], bf[4][2];
#pragma unroll
            for (int mi = 0; mi < 4; mi++) {
                int m0 = wm + mi * 16 + g;
                af[mi][0] = As[m0][kk + tg];
                af[mi][1] = As[m0 + 8][kk + tg];
                af[mi][2] = As[m0][kk + tg + 4];
                af[mi][3] = As[m0 + 8][kk + tg + 4];
            }
#pragma unroll
            for (int ni = 0; ni < 4; ni++) {
                int n0 = wn + ni * 8 + g;
                bf[ni][0] = Bs[kk + tg][n0];
                bf[ni][1] = Bs[kk + tg + 4][n0];
            }
#pragma unroll
            for (int mi = 0; mi < 4; mi++)
#pragma unroll
                for (int ni = 0; ni < 4; ni++)
                    mma_tf32(acc[mi][ni], af[mi], bf[ni]);
        }
        __syncthreads();
    }

    // ---------------- epilogue ----------------
#pragma unroll
    for (int mi = 0; mi < 4; mi++) {
#pragma unroll
        for (int ni = 0; ni < 4; ni++) {
#pragma unroll
            for (int half = 0; half < 2; half++) {
                int row = bm + wm + mi * 16 + g + half * 8;
                int col = bn + wn + ni * 8 + tg * 2;
                float v0 = acc[mi][ni][half * 2 + 0];
                float v1 = acc[mi][ni][half * 2 + 1];
                if (EPI == EPI_QKV) {
                    int s  = col >> 10;
                    int h  = (col >> 6) & (H_ - 1);
                    int d0 = col & 63;
                    int bb = row >> 11;
                    int t  = row & 2047;
                    float* dst = ((s == 0) ? g_q : ((s == 1) ? g_k : g_v))
                                 + (((size_t)(bb * H_ + h) * T_) + t) * HD_ + d0;
                    *(float2*)dst = make_float2(v0, v1);
                } else if (EPI == EPI_BIAS_RELU) {
                    float2 bv = *(const float2*)(bias + col);
                    float2 o = make_float2(fmaxf(v0 + bv.x, 0.f), fmaxf(v1 + bv.y, 0.f));
                    *(float2*)(Cout + (size_t)row * N + col) = o;
                } else {
                    float2 bv = *(const float2*)(bias + col);
                    float2 rv = *(const float2*)(res + (size_t)row * N + col);
                    float2 o = make_float2(v0 + bv.x + rv.x, v1 + bv.y + rv.y);
                    *(float2*)(Cout + (size_t)row * N + col) = o;
                }
            }
        }
    }
}

// ---------------- causal flash attention, fp32 ----------------
__global__ __launch_bounds__(256)
void attn_kernel() {
    __shared__ __align__(16) float Qs[64][64];
    __shared__ __align__(16) float Ks[64][32];
    __shared__ __align__(16) float Vs[32][64];
    __shared__ float Ss[64][33];
    __shared__ float row_alpha[64];
    __shared__ float row_l[64];

    const int tid = threadIdx.x;
    const int bh  = blockIdx.y;
    const int qr0 = blockIdx.x * 64;
    const float* qb = g_q + (size_t)bh * T_ * HD_;
    const float* kb = g_k + (size_t)bh * T_ * HD_;
    const float* vb = g_v + (size_t)bh * T_ * HD_;

    for (int i = tid; i < 1024; i += 256) {
        int r  = i >> 4;
        int d4 = (i & 15) << 2;
        float4 qv = *(const float4*)(qb + (size_t)(qr0 + r) * HD_ + d4);
        Qs[d4 + 0][r] = qv.x * 0.125f;
        Qs[d4 + 1][r] = qv.y * 0.125f;
        Qs[d4 + 2][r] = qv.z * 0.125f;
        Qs[d4 + 3][r] = qv.w * 0.125f;
    }

    const int ty = tid >> 3;
    const int tx = tid & 7;
    const int r0 = ty * 2;

    float oacc[2][8];
#pragma unroll
    for (int i = 0; i < 2; i++)
#pragma unroll
        for (int j = 0; j < 8; j++) oacc[i][j] = 0.f;
    float m_reg = -1e30f, l_reg = 0.f;

    for (int kc0 = 0; kc0 <= qr0 + 32; kc0 += 32) {
        __syncthreads();
        for (int i = tid; i < 512; i += 256) {
            int c  = i >> 4;
            int d4 = (i & 15) << 2;
            float4 kv = *(const float4*)(kb + (size_t)(kc0 + c) * HD_ + d4);
            Ks[d4 + 0][c] = kv.x;
            Ks[d4 + 1][c] = kv.y;
            Ks[d4 + 2][c] = kv.z;
            Ks[d4 + 3][c] = kv.w;
            *(float4*)&Vs[c][d4] = *(const float4*)(vb + (size_t)(kc0 + c) * HD_ + d4);
        }
        __syncthreads();

        float sacc[2][4];
#pragma unroll
        for (int i = 0; i < 2; i++)
#pragma unroll
            for (int j = 0; j < 4; j++) sacc[i][j] = 0.f;
#pragma unroll
        for (int d = 0; d < 64; d++) {
            float q0 = Qs[d][r0];
            float q1 = Qs[d][r0 + 1];
            float4 kv = *(const float4*)&Ks[d][tx * 4];
            sacc[0][0] += q0 * kv.x; sacc[0][1] += q0 * kv.y;
            sacc[0][2] += q0 * kv.z; sacc[0][3] += q0 * kv.w;
            sacc[1][0] += q1 * kv.x; sacc[1][1] += q1 * kv.y;
            sacc[1][2] += q1 * kv.z; sacc[1][3] += q1 * kv.w;
        }
        bool need_mask = (kc0 + 31 > qr0);
#pragma unroll
        for (int i = 0; i < 2; i++) {
            int rg = qr0 + r0 + i;
#pragma unroll
            for (int j = 0; j < 4; j++) {
                int cg = kc0 + tx * 4 + j;
                float sv = sacc[i][j];
                if (need_mask && cg > rg) sv = -1e30f;
                Ss[r0 + i][tx * 4 + j] = sv;
            }
        }
        __syncthreads();

        if (tid < 64) {
            float mx = m_reg;
#pragma unroll
            for (int c = 0; c < 32; c++) mx = fmaxf(mx, Ss[tid][c]);
            float alpha = __expf(m_reg - mx);
            float sum = 0.f;
#pragma unroll
            for (int c = 0; c < 32; c++) {
                float p = __expf(Ss[tid][c] - mx);
                Ss[tid][c] = p;
                sum += p;
            }
            m_reg = mx;
            l_reg = l_reg * alpha + sum;
            row_alpha[tid] = alpha;
        }
        __syncthreads();

        float a0 = row_alpha[r0];
        float a1 = row_alpha[r0 + 1];
#pragma unroll
        for (int j = 0; j < 8; j++) { oacc[0][j] *= a0; oacc[1][j] *= a1; }
#pragma unroll
        for (int c = 0; c < 32; c++) {
            float p0 = Ss[r0][c];
            float p1 = Ss[r0 + 1][c];
            float4 v0 = *(const float4*)&Vs[c][tx * 8];
            float4 v1 = *(const float4*)&Vs[c][tx * 8 + 4];
            oacc[0][0] += p0 * v0.x; oacc[0][1] += p0 * v0.y;
            oacc[0][2] += p0 * v0.z; oacc[0][3] += p0 * v0.w;
            oacc[0][4] += p0 * v1.x; oacc[0][5] += p0 * v1.y;
            oacc[0][6] += p0 * v1.z; oacc[0][7] += p0 * v1.w;
            oacc[1][0] += p1 * v0.x; oacc[1][1] += p1 * v0.y;
            oacc[1][2] += p1 * v0.z; oacc[1][3] += p1 * v0.w;
            oacc[1][4] += p1 * v1.x; oacc[1][5] += p1 * v1.y;
            oacc[1][6] += p1 * v1.z; oacc[1][7] += p1 * v1.w;
        }
    }

    if (tid < 64) row_l[tid] = l_reg;
    __syncthreads();

    const int b = bh >> 4;
    const int h = bh & 15;
#pragma unroll
    for (int i = 0; i < 2; i++) {
        int t = qr0 + r0 + i;
        float inv = 1.f / row_l[r0 + i];
        float* dst = g_attn + ((size_t)(b * T_ + t)) * C_ + h * HD_ + tx * 8;
        float4 o0 = make_float4(oacc[i][0] * inv, oacc[i][1] * inv,
                                oacc[i][2] * inv, oacc[i][3] * inv);
        float4 o1 = make_float4(oacc[i][4] * inv, oacc[i][5] * inv,
                                oacc[i][6] * inv, oacc[i][7] * inv);
        *(float4*)dst       = o0;
        *(float4*)(dst + 4) = o1;
    }
}

// ---------------- LayerNorm over C=1024, 1 row per block ----------------
__global__ __launch_bounds__(256)
void ln_kernel(const float* __restrict__ x, const float* __restrict__ g,
               const float* __restrict__ beta, float* __restrict__ y) {
    const int row = blockIdx.x;
    const int tid = threadIdx.x;
    const float* xr = x + (size_t)row * C_;

    float4 v = *(const float4*)(xr + tid * 4);
    float s  = v.x + v.y + v.z + v.w;
    float s2 = v.x * v.x + v.y * v.y + v.z * v.z + v.w * v.w;
#pragma unroll
    for (int o = 16; o > 0; o >>= 1) {
        s  += __shfl_xor_sync(0xFFFFFFFFu, s, o);
        s2 += __shfl_xor_sync(0xFFFFFFFFu, s2, o);
    }
    __shared__ float sh[16];
    __shared__ float mean_sh, istd_sh;
    int w = tid >> 5, l = tid & 31;
    if (l == 0) { sh[w] = s; sh[w + 8] = s2; }
    __syncthreads();
    if (tid == 0) {
        float ts = 0.f, ts2 = 0.f;
#pragma unroll
        for (int i = 0; i < 8; i++) { ts += sh[i]; ts2 += sh[i + 8]; }
        float mean = ts * (1.f / C_);
        float var  = ts2 * (1.f / C_) - mean * mean;
        mean_sh = mean;
        istd_sh = rsqrtf(var + 1e-5f);
    }
    __syncthreads();
    float mean = mean_sh, istd = istd_sh;
    float4 gv = *(const float4*)(g + tid * 4);
    float4 bv = *(const float4*)(beta + tid * 4);
    float4 out;
    out.x = (v.x - mean) * istd * gv.x + bv.x;
    out.y = (v.y - mean) * istd * gv.y + bv.y;
    out.z = (v.z - mean) * istd * gv.z + bv.z;
    out.w = (v.w - mean) * istd * gv.w + bv.w;
    *(float4*)(y + (size_t)row * C_ + tid * 4) = out;
}

// ---------------- launch ----------------
extern "C" void kernel_launch(void* const* d_in, const int* in_sizes, int n_in,
                              void* d_out, int out_size) {
    (void)in_sizes; (void)n_in; (void)out_size;
    const float* x   = (const float*)d_in[0];
    const float* Wq  = (const float*)d_in[1];
    const float* Wk  = (const float*)d_in[2];
    const float* Wv  = (const float*)d_in[3];
    const float* Wp  = (const float*)d_in[4];
    const float* bp  = (const float*)d_in[5];
    const float* W1  = (const float*)d_in[6];
    const float* b1  = (const float*)d_in[7];
    const float* W2  = (const float*)d_in[8];
    const float* b2  = (const float*)d_in[9];
    const float* g1  = (const float*)d_in[10];
    const float* be1 = (const float*)d_in[11];
    const float* g2  = (const float*)d_in[12];
    const float* be2 = (const float*)d_in[13];

    void *p_wqkv_, *p_attn_, *p_h1_, *p_x1_, *p_ff_, *p_h2_;
    cudaGetSymbolAddress(&p_wqkv_, g_Wqkv);
    cudaGetSymbolAddress(&p_attn_, g_attn);
    cudaGetSymbolAddress(&p_h1_,   g_h1);
    cudaGetSymbolAddress(&p_x1_,   g_x1);
    cudaGetSymbolAddress(&p_ff_,   g_ff);
    cudaGetSymbolAddress(&p_h2_,   g_h2);
    float* p_wqkv = (float*)p_wqkv_;
    float* p_attn = (float*)p_attn_;
    float* p_h1   = (float*)p_h1_;
    float* p_x1   = (float*)p_x1_;
    float* p_ff   = (float*)p_ff_;
    float* p_h2   = (float*)p_h2_;

    // 1. pack qkv weights -> [C, 3C]
    pack_qkv_kernel<<<(C_ * 3 * C_ + 255) / 256, 256>>>(Wq, Wk, Wv);
    // 2. QKV projection (tensor cores via mma.sync tf32)
    gemm_tc<EPI_QKV><<<dim3(3 * C_ / BN, M_ / BM), 256>>>(
        x, p_wqkv, nullptr, nullptr, nullptr, M_, 3 * C_, C_);
    // 3. causal attention -> concat layout
    attn_kernel<<<dim3(T_ / 64, B_ * H_), 256>>>();
    // 4. out proj + bias + residual
    gemm_tc<EPI_BIAS_RES><<<dim3(C_ / BN, M_ / BM), 256>>>(
        p_attn, Wp, bp, x, p_h1, M_, C_, C_);
    // 5. LN1
    ln_kernel<<<M_, 256>>>(p_h1, g1, be1, p_x1);
    // 6. FFN up + relu
    gemm_tc<EPI_BIAS_RELU><<<dim3(FF_ / BN, M_ / BM), 256>>>(
        p_x1, W1, b1, nullptr, p_ff, M_, FF_, C_);
    // 7. FFN down + bias + residual
    gemm_tc<EPI_BIAS_RES><<<dim3(C_ / BN, M_ / BM), 256>>>(
        p_ff, W2, b2, p_x1, p_h2, M_, C_, FF_);
    // 8. LN2 -> d_out
    ln_kernel<<<M_, 256>>>(p_h2, g2, be2, (float*)d_out);
}

// round 5
// speedup vs baseline: 3.1402x; 1.7945x over previous
#include <cuda_runtime.h>
#include <cstdint>
#include <cmath>

#define B_  2
#define T_  2048
#define C_  1024
#define H_  16
#define HD_ 64
#define M_  (B_ * T_)     // 4096 rows
#define FF_ (4 * C_)      // 4096

// ---------------- scratch (static device allocations; allowed) ----------------
__device__ float g_Wqkv[C_ * 3 * C_];          // packed [C, 3C] qkv weight
__device__ float g_q[B_ * H_ * T_ * HD_];      // [b,h,t,d]
__device__ float g_k[B_ * H_ * T_ * HD_];
__device__ float g_v[B_ * H_ * T_ * HD_];
__device__ float g_attn[M_ * C_];              // attention out, concat layout
__device__ float g_h1[M_ * C_];                // x + attn_proj
__device__ float g_x1[M_ * C_];                // LN1 out
__device__ float g_ff[M_ * FF_];               // relu(x1 W1 + b1)
__device__ float g_h2[M_ * C_];                // x1 + ffn out

// ---------------- tf32 helpers ----------------
__device__ __forceinline__ uint32_t f2tf32(float f) {
    uint32_t r;
    asm("cvt.rna.tf32.f32 %0, %1;" : "=r"(r) : "f"(f));
    return r;
}

// m16n8k8 tf32 MMA (arch-generic, sm_80+)
__device__ __forceinline__ void mma_tf32(float* d, const uint32_t* a, const uint32_t* b) {
    asm volatile(
        "mma.sync.aligned.m16n8k8.row.col.f32.tf32.tf32.f32 "
        "{%0,%1,%2,%3}, {%4,%5,%6,%7}, {%8,%9}, {%0,%1,%2,%3};\n"
        : "+f"(d[0]), "+f"(d[1]), "+f"(d[2]), "+f"(d[3])
        : "r"(a[0]), "r"(a[1]), "r"(a[2]), "r"(a[3]),
          "r"(b[0]), "r"(b[1]));
}

// ---------------- weight pack ----------------
__global__ void pack_qkv_kernel(const float* __restrict__ Wq,
                                const float* __restrict__ Wk,
                                const float* __restrict__ Wv) {
    int idx = blockIdx.x * blockDim.x + threadIdx.x;
    if (idx >= C_ * 3 * C_) return;
    int c   = idx / (3 * C_);
    int rem = idx - c * (3 * C_);
    int s   = rem >> 10;
    int r2  = rem & 1023;
    int h   = r2 >> 6;
    int d   = r2 & 63;
    const float* W = (s == 0) ? Wq : ((s == 1) ? Wk : Wv);
    g_Wqkv[idx] = W[(h * C_ + c) * HD_ + d];
}

// ============ tf32 mma.sync GEMM: 128x128 CTA tile, BK=32, 8 warps ============
constexpr int EPI_QKV       = 0;
constexpr int EPI_BIAS_RELU = 1;
constexpr int EPI_BIAS_RES  = 2;

#define BM 128
#define BN 128
#define BK 32
#define AS_STRIDE 36
#define BS_STRIDE 136

template <int EPI>
__global__ __launch_bounds__(256, 1)
void gemm_tc(const float* __restrict__ A, const float* __restrict__ Bmat,
             const float* __restrict__ bias, const float* __restrict__ res,
             float* __restrict__ Cout, int M, int N, int K) {
    __shared__ __align__(16) uint32_t As[BM][AS_STRIDE];   // [m][k] tf32 bits
    __shared__ __align__(16) uint32_t Bs[BK][BS_STRIDE];   // [k][n] tf32 bits

    const int tid = threadIdx.x;
    const int wid = tid >> 5;
    const int lane = tid & 31;
    const int g  = lane >> 2;
    const int tg = lane & 3;
    const int wm = (wid >> 2) * 64;
    const int wn = (wid & 3) * 32;
    const int bm = blockIdx.y * BM;
    const int bn = blockIdx.x * BN;

    float acc[4][4][4];
#pragma unroll
    for (int mi = 0; mi < 4; mi++)
#pragma unroll
        for (int ni = 0; ni < 4; ni++)
#pragma unroll
            for (int j = 0; j < 4; j++) acc[mi][ni][j] = 0.f;

    const int KT = K / BK;

    float4 aR[4], bR[4];
    {
        const float* Ag = A + (size_t)bm * K;
        const float* Bg = Bmat + bn;
#pragma unroll
        for (int i = 0; i < 4; i++) {
            int f = i * 256 + tid;
            int r = f >> 3, c = f & 7;
            aR[i] = *(const float4*)(Ag + (size_t)r * K + c * 4);
            int k = f >> 5, n4 = f & 31;
            bR[i] = *(const float4*)(Bg + (size_t)k * N + n4 * 4);
        }
    }

    for (int kt = 0; kt < KT; ++kt) {
#pragma unroll
        for (int i = 0; i < 4; i++) {
            int f = i * 256 + tid;
            int r = f >> 3, c = f & 7;
            uint4 t;
            t.x = f2tf32(aR[i].x); t.y = f2tf32(aR[i].y);
            t.z = f2tf32(aR[i].z); t.w = f2tf32(aR[i].w);
            *(uint4*)&As[r][c * 4] = t;
            int k = f >> 5, n4 = f & 31;
            uint4 u;
            u.x = f2tf32(bR[i].x); u.y = f2tf32(bR[i].y);
            u.z = f2tf32(bR[i].z); u.w = f2tf32(bR[i].w);
            *(uint4*)&Bs[k][n4 * 4] = u;
        }
        __syncthreads();

        if (kt + 1 < KT) {
            const int k0 = (kt + 1) * BK;
            const float* Ag = A + (size_t)bm * K + k0;
            const float* Bg = Bmat + (size_t)k0 * N + bn;
#pragma unroll
            for (int i = 0; i < 4; i++) {
                int f = i * 256 + tid;
                int r = f >> 3, c = f & 7;
                aR[i] = *(const float4*)(Ag + (size_t)r * K + c * 4);
                int k = f >> 5, n4 = f & 31;
                bR[i] = *(const float4*)(Bg + (size_t)k * N + n4 * 4);
            }
        }

#pragma unroll
        for (int kk8 = 0; kk8 < 4; kk8++) {
            const int kk = kk8 * 8;
            uint32_t af[4][4], bf[4][2];
#pragma unroll
            for (int mi = 0; mi < 4; mi++) {
                int m0 = wm + mi * 16 + g;
                af[mi][0] = As[m0][kk + tg];
                af[mi][1] = As[m0 + 8][kk + tg];
                af[mi][2] = As[m0][kk + tg + 4];
                af[mi][3] = As[m0 + 8][kk + tg + 4];
            }
#pragma unroll
            for (int ni = 0; ni < 4; ni++) {
                int n0 = wn + ni * 8 + g;
                bf[ni][0] = Bs[kk + tg][n0];
                bf[ni][1] = Bs[kk + tg + 4][n0];
            }
#pragma unroll
            for (int mi = 0; mi < 4; mi++)
#pragma unroll
                for (int ni = 0; ni < 4; ni++)
                    mma_tf32(acc[mi][ni], af[mi], bf[ni]);
        }
        __syncthreads();
    }

#pragma unroll
    for (int mi = 0; mi < 4; mi++) {
#pragma unroll
        for (int ni = 0; ni < 4; ni++) {
#pragma unroll
            for (int half = 0; half < 2; half++) {
                int row = bm + wm + mi * 16 + g + half * 8;
                int col = bn + wn + ni * 8 + tg * 2;
                float v0 = acc[mi][ni][half * 2 + 0];
                float v1 = acc[mi][ni][half * 2 + 1];
                if (EPI == EPI_QKV) {
                    int s  = col >> 10;
                    int h  = (col >> 6) & (H_ - 1);
                    int d0 = col & 63;
                    int bb = row >> 11;
                    int t  = row & 2047;
                    float* dst = ((s == 0) ? g_q : ((s == 1) ? g_k : g_v))
                                 + (((size_t)(bb * H_ + h) * T_) + t) * HD_ + d0;
                    *(float2*)dst = make_float2(v0, v1);
                } else if (EPI == EPI_BIAS_RELU) {
                    float2 bv = *(const float2*)(bias + col);
                    float2 o = make_float2(fmaxf(v0 + bv.x, 0.f), fmaxf(v1 + bv.y, 0.f));
                    *(float2*)(Cout + (size_t)row * N + col) = o;
                } else {
                    float2 bv = *(const float2*)(bias + col);
                    float2 rv = *(const float2*)(res + (size_t)row * N + col);
                    float2 o = make_float2(v0 + bv.x + rv.x, v1 + bv.y + rv.y);
                    *(float2*)(Cout + (size_t)row * N + col) = o;
                }
            }
        }
    }
}

// ====== tensor-core causal flash attention (tf32 mma.sync) ======
// CTA: 128 q-rows, 8 warps (16 rows each), key blocks of 64, HD=64.
// SMEM (floats): Ps[128][68] (Q stage, then P), Kst[64][68], Vst[64][72]
#define PS_STRIDE 68
#define KS_STRIDE 68
#define VS_STRIDE 72
#define ATTN_SMEM_FLOATS (128 * PS_STRIDE + 64 * KS_STRIDE + 64 * VS_STRIDE)
#define ATTN_SMEM_BYTES  (ATTN_SMEM_FLOATS * 4)

__global__ __launch_bounds__(256, 1)
void attn_tc_kernel() {
    extern __shared__ float sm[];
    float* Ps  = sm;                               // [128][68]
    float* Kst = sm + 128 * PS_STRIDE;             // [64][68]
    float* Vst = Kst + 64 * KS_STRIDE;             // [64][72]
    uint32_t* Pu = (uint32_t*)Ps;
    uint32_t* Ku = (uint32_t*)Kst;
    uint32_t* Vu = (uint32_t*)Vst;

    const int tid  = threadIdx.x;
    const int wid  = tid >> 5;
    const int lane = tid & 31;
    const int g    = lane >> 2;
    const int tg   = lane & 3;
    const int bh   = blockIdx.y;
    const int qi   = gridDim.x - 1 - blockIdx.x;   // heavy tiles first
    const int qr0  = qi * 128;

    const float* qb = g_q + (size_t)bh * T_ * HD_;
    const float* kb = g_k + (size_t)bh * T_ * HD_;
    const float* vb = g_v + (size_t)bh * T_ * HD_;

    // ---- stage Q (scaled, tf32) into Ps ----
    for (int i = tid; i < 2048; i += 256) {        // 128 rows x 16 float4
        int r  = i >> 4;
        int c4 = (i & 15) << 2;
        float4 v = *(const float4*)(qb + (size_t)(qr0 + r) * HD_ + c4);
        float4 o;
        o.x = __uint_as_float(f2tf32(v.x * 0.125f));
        o.y = __uint_as_float(f2tf32(v.y * 0.125f));
        o.z = __uint_as_float(f2tf32(v.z * 0.125f));
        o.w = __uint_as_float(f2tf32(v.w * 0.125f));
        *(float4*)(Ps + r * PS_STRIDE + c4) = o;
    }
    __syncthreads();

    // ---- extract Q frags to registers ----
    const int m0 = wid * 16 + g;
    uint32_t qf[8][4];
#pragma unroll
    for (int c = 0; c < 8; c++) {
        int kk = c * 8;
        qf[c][0] = Pu[m0 * PS_STRIDE + kk + tg];
        qf[c][1] = Pu[(m0 + 8) * PS_STRIDE + kk + tg];
        qf[c][2] = Pu[m0 * PS_STRIDE + kk + tg + 4];
        qf[c][3] = Pu[(m0 + 8) * PS_STRIDE + kk + tg + 4];
    }
    __syncthreads();   // Ps now reusable as P buffer

    float m_s[2] = {-1e30f, -1e30f};
    float l_s[2] = {0.f, 0.f};
    float oacc[8][4];
#pragma unroll
    for (int ni = 0; ni < 8; ni++)
#pragma unroll
        for (int j = 0; j < 4; j++) oacc[ni][j] = 0.f;

    const int nblocks = qr0 / 64 + 2;
    for (int ib = 0; ib < nblocks; ib++) {
        const int kc0 = ib * 64;
        __syncthreads();   // protect Kst/Vst from prior-iter readers
        // ---- load K, V tiles (natural layout, tf32) ----
        for (int i = tid; i < 1024; i += 256) {    // 64 rows x 16 float4
            int key = i >> 4;
            int d4  = (i & 15) << 2;
            float4 kv = *(const float4*)(kb + (size_t)(kc0 + key) * HD_ + d4);
            float4 ko;
            ko.x = __uint_as_float(f2tf32(kv.x));
            ko.y = __uint_as_float(f2tf32(kv.y));
            ko.z = __uint_as_float(f2tf32(kv.z));
            ko.w = __uint_as_float(f2tf32(kv.w));
            *(float4*)(Kst + key * KS_STRIDE + d4) = ko;
            float4 vv = *(const float4*)(vb + (size_t)(kc0 + key) * HD_ + d4);
            float4 vo;
            vo.x = __uint_as_float(f2tf32(vv.x));
            vo.y = __uint_as_float(f2tf32(vv.y));
            vo.z = __uint_as_float(f2tf32(vv.z));
            vo.w = __uint_as_float(f2tf32(vv.w));
            *(float4*)(Vst + key * VS_STRIDE + d4) = vo;
        }
        __syncthreads();

        // ---- S = Q K^T : B[k=d][n=key] = Kst[key][d] (natural) ----
        float sacc[8][4];
#pragma unroll
        for (int ni = 0; ni < 8; ni++)
#pragma unroll
            for (int j = 0; j < 4; j++) sacc[ni][j] = 0.f;
#pragma unroll
        for (int c = 0; c < 8; c++) {
            int kk = c * 8;
            uint32_t bf[8][2];
#pragma unroll
            for (int ni = 0; ni < 8; ni++) {
                int n0 = ni * 8 + g;
                bf[ni][0] = Ku[n0 * KS_STRIDE + kk + tg];
                bf[ni][1] = Ku[n0 * KS_STRIDE + kk + tg + 4];
            }
#pragma unroll
            for (int ni = 0; ni < 8; ni++)
                mma_tf32(sacc[ni], qf[c], bf[ni]);
        }

        // ---- causal mask (only needed near the diagonal) ----
        if (kc0 + 63 > qr0 + wid * 16) {
#pragma unroll
            for (int ni = 0; ni < 8; ni++) {
#pragma unroll
                for (int j = 0; j < 4; j++) {
                    int row = qr0 + wid * 16 + g + ((j >= 2) ? 8 : 0);
                    int col = kc0 + ni * 8 + tg * 2 + (j & 1);
                    if (col > row) sacc[ni][j] = -1e30f;
                }
            }
        }

        // ---- online softmax (registers + quad shuffles) ----
#pragma unroll
        for (int r = 0; r < 2; r++) {
            float mx = m_s[r];
#pragma unroll
            for (int ni = 0; ni < 8; ni++)
                mx = fmaxf(mx, fmaxf(sacc[ni][r * 2], sacc[ni][r * 2 + 1]));
            mx = fmaxf(mx, __shfl_xor_sync(0xFFFFFFFFu, mx, 1));
            mx = fmaxf(mx, __shfl_xor_sync(0xFFFFFFFFu, mx, 2));
            float alpha = __expf(m_s[r] - mx);
            m_s[r] = mx;
            float sum = 0.f;
            const int mrow = (r ? m0 + 8 : m0);
#pragma unroll
            for (int ni = 0; ni < 8; ni++) {
                float p0 = __expf(sacc[ni][r * 2]     - mx);
                float p1 = __expf(sacc[ni][r * 2 + 1] - mx);
                sum += p0 + p1;
                float2 st;
                st.x = __uint_as_float(f2tf32(p0));
                st.y = __uint_as_float(f2tf32(p1));
                *(float2*)(Ps + mrow * PS_STRIDE + ni * 8 + tg * 2) = st;
            }
            sum += __shfl_xor_sync(0xFFFFFFFFu, sum, 1);
            sum += __shfl_xor_sync(0xFFFFFFFFu, sum, 2);
            l_s[r] = l_s[r] * alpha + sum;
#pragma unroll
            for (int ni = 0; ni < 8; ni++) {
                oacc[ni][r * 2]     *= alpha;
                oacc[ni][r * 2 + 1] *= alpha;
            }
        }
        __syncwarp();   // P rows are warp-private

        // ---- O += P V : A=Ps rows (warp-own), B[k=key][n=d] = Vst natural ----
#pragma unroll
        for (int c = 0; c < 8; c++) {
            int kk = c * 8;
            uint32_t af[4];
            af[0] = Pu[m0 * PS_STRIDE + kk + tg];
            af[1] = Pu[(m0 + 8) * PS_STRIDE + kk + tg];
            af[2] = Pu[m0 * PS_STRIDE + kk + tg + 4];
            af[3] = Pu[(m0 + 8) * PS_STRIDE + kk + tg + 4];
            uint32_t bf[8][2];
#pragma unroll
            for (int ni = 0; ni < 8; ni++) {
                int n0 = ni * 8 + g;
                bf[ni][0] = Vu[(kk + tg) * VS_STRIDE + n0];
                bf[ni][1] = Vu[(kk + tg + 4) * VS_STRIDE + n0];
            }
#pragma unroll
            for (int ni = 0; ni < 8; ni++)
                mma_tf32(oacc[ni], af, bf[ni]);
        }
    }

    // ---- epilogue: normalize and store in concat layout ----
    const int b = bh >> 4;
    const int h = bh & 15;
#pragma unroll
    for (int r = 0; r < 2; r++) {
        float inv = 1.f / l_s[r];
        int t = qr0 + m0 + (r ? 8 : 0);
        float* dst = g_attn + ((size_t)(b * T_ + t)) * C_ + h * HD_;
#pragma unroll
        for (int ni = 0; ni < 8; ni++) {
            float2 o;
            o.x = oacc[ni][r * 2]     * inv;
            o.y = oacc[ni][r * 2 + 1] * inv;
            *(float2*)(dst + ni * 8 + tg * 2) = o;
        }
    }
}

// ---------------- LayerNorm over C=1024, 1 row per block ----------------
__global__ __launch_bounds__(256)
void ln_kernel(const float* __restrict__ x, const float* __restrict__ g,
               const float* __restrict__ beta, float* __restrict__ y) {
    const int row = blockIdx.x;
    const int tid = threadIdx.x;
    const float* xr = x + (size_t)row * C_;

    float4 v = *(const float4*)(xr + tid * 4);
    float s  = v.x + v.y + v.z + v.w;
    float s2 = v.x * v.x + v.y * v.y + v.z * v.z + v.w * v.w;
#pragma unroll
    for (int o = 16; o > 0; o >>= 1) {
        s  += __shfl_xor_sync(0xFFFFFFFFu, s, o);
        s2 += __shfl_xor_sync(0xFFFFFFFFu, s2, o);
    }
    __shared__ float sh[16];
    __shared__ float mean_sh, istd_sh;
    int w = tid >> 5, l = tid & 31;
    if (l == 0) { sh[w] = s; sh[w + 8] = s2; }
    __syncthreads();
    if (tid == 0) {
        float ts = 0.f, ts2 = 0.f;
#pragma unroll
        for (int i = 0; i < 8; i++) { ts += sh[i]; ts2 += sh[i + 8]; }
        float mean = ts * (1.f / C_);
        float var  = ts2 * (1.f / C_) - mean * mean;
        mean_sh = mean;
        istd_sh = rsqrtf(var + 1e-5f);
    }
    __syncthreads();
    float mean = mean_sh, istd = istd_sh;
    float4 gv = *(const float4*)(g + tid * 4);
    float4 bv = *(const float4*)(beta + tid * 4);
    float4 out;
    out.x = (v.x - mean) * istd * gv.x + bv.x;
    out.y = (v.y - mean) * istd * gv.y + bv.y;
    out.z = (v.z - mean) * istd * gv.z + bv.z;
    out.w = (v.w - mean) * istd * gv.w + bv.w;
    *(float4*)(y + (size_t)row * C_ + tid * 4) = out;
}

// ---------------- launch ----------------
extern "C" void kernel_launch(void* const* d_in, const int* in_sizes, int n_in,
                              void* d_out, int out_size) {
    (void)in_sizes; (void)n_in; (void)out_size;
    const float* x   = (const float*)d_in[0];
    const float* Wq  = (const float*)d_in[1];
    const float* Wk  = (const float*)d_in[2];
    const float* Wv  = (const float*)d_in[3];
    const float* Wp  = (const float*)d_in[4];
    const float* bp  = (const float*)d_in[5];
    const float* W1  = (const float*)d_in[6];
    const float* b1  = (const float*)d_in[7];
    const float* W2  = (const float*)d_in[8];
    const float* b2  = (const float*)d_in[9];
    const float* g1  = (const float*)d_in[10];
    const float* be1 = (const float*)d_in[11];
    const float* g2  = (const float*)d_in[12];
    const float* be2 = (const float*)d_in[13];

    void *p_wqkv_, *p_attn_, *p_h1_, *p_x1_, *p_ff_, *p_h2_;
    cudaGetSymbolAddress(&p_wqkv_, g_Wqkv);
    cudaGetSymbolAddress(&p_attn_, g_attn);
    cudaGetSymbolAddress(&p_h1_,   g_h1);
    cudaGetSymbolAddress(&p_x1_,   g_x1);
    cudaGetSymbolAddress(&p_ff_,   g_ff);
    cudaGetSymbolAddress(&p_h2_,   g_h2);
    float* p_wqkv = (float*)p_wqkv_;
    float* p_attn = (float*)p_attn_;
    float* p_h1   = (float*)p_h1_;
    float* p_x1   = (float*)p_x1_;
    float* p_ff   = (float*)p_ff_;
    float* p_h2   = (float*)p_h2_;

    cudaFuncSetAttribute(attn_tc_kernel,
                         cudaFuncAttributeMaxDynamicSharedMemorySize, ATTN_SMEM_BYTES);

    // 1. pack qkv weights -> [C, 3C]
    pack_qkv_kernel<<<(C_ * 3 * C_ + 255) / 256, 256>>>(Wq, Wk, Wv);
    // 2. QKV projection (tensor cores)
    gemm_tc<EPI_QKV><<<dim3(3 * C_ / BN, M_ / BM), 256>>>(
        x, p_wqkv, nullptr, nullptr, nullptr, M_, 3 * C_, C_);
    // 3. causal attention (tensor cores) -> concat layout
    attn_tc_kernel<<<dim3(T_ / 128, B_ * H_), 256, ATTN_SMEM_BYTES>>>();
    // 4. out proj + bias + residual
    gemm_tc<EPI_BIAS_RES><<<dim3(C_ / BN, M_ / BM), 256>>>(
        p_attn, Wp, bp, x, p_h1, M_, C_, C_);
    // 5. LN1
    ln_kernel<<<M_, 256>>>(p_h1, g1, be1, p_x1);
    // 6. FFN up + relu
    gemm_tc<EPI_BIAS_RELU><<<dim3(FF_ / BN, M_ / BM), 256>>>(
        p_x1, W1, b1, nullptr, p_ff, M_, FF_, C_);
    // 7. FFN down + bias + residual
    gemm_tc<EPI_BIAS_RES><<<dim3(C_ / BN, M_ / BM), 256>>>(
        p_ff, W2, b2, p_x1, p_h2, M_, C_, FF_);
    // 8. LN2 -> d_out
    ln_kernel<<<M_, 256>>>(p_h2, g2, be2, (float*)d_out);
}

// round 8
// speedup vs baseline: 3.7256x; 1.1864x over previous
#include <cuda_runtime.h>
#include <cuda_fp16.h>
#include <cstdint>
#include <cmath>

#define B_  2
#define T_  2048
#define C_  1024
#define H_  16
#define HD_ 64
#define M_  (B_ * T_)     // 4096 rows
#define FF_ (4 * C_)      // 4096

// ---------------- scratch (static device allocations; allowed) ----------------
__device__ float  g_Wqkv[C_ * 3 * C_];           // packed [C, 3C] qkv weight
__device__ __half g_qh[B_ * H_ * T_ * HD_];      // [b,h][t][d], pre-scaled 0.125
__device__ __half g_kh[B_ * H_ * T_ * HD_];      // [b,h][t][d]
__device__ __half g_vTh[B_ * H_ * HD_ * T_];     // [b,h][d][t]  (transposed!)
__device__ float  g_attn[M_ * C_];               // attention out, concat layout
__device__ float  g_h1[M_ * C_];
__device__ float  g_x1[M_ * C_];
__device__ float  g_ff[M_ * FF_];
__device__ float  g_h2[M_ * C_];

// ---------------- helpers ----------------
__device__ __forceinline__ uint32_t f2tf32(float f) {
    uint32_t r;
    asm("cvt.rna.tf32.f32 %0, %1;" : "=r"(r) : "f"(f));
    return r;
}
__device__ __forceinline__ uint32_t h22u(__half2 h) {
    __half2_raw hr = *reinterpret_cast<__half2_raw*>(&h);
    return (uint32_t)hr.x | ((uint32_t)hr.y << 16);
}
__device__ __forceinline__ void mma_tf32(float* d, const uint32_t* a, const uint32_t* b) {
    asm volatile(
        "mma.sync.aligned.m16n8k8.row.col.f32.tf32.tf32.f32 "
        "{%0,%1,%2,%3}, {%4,%5,%6,%7}, {%8,%9}, {%0,%1,%2,%3};\n"
        : "+f"(d[0]), "+f"(d[1]), "+f"(d[2]), "+f"(d[3])
        : "r"(a[0]), "r"(a[1]), "r"(a[2]), "r"(a[3]),
          "r"(b[0]), "r"(b[1]));
}
__device__ __forceinline__ void mma_f16(float* d, const uint32_t* a, const uint32_t* b) {
    asm volatile(
        "mma.sync.aligned.m16n8k16.row.col.f32.f16.f16.f32 "
        "{%0,%1,%2,%3}, {%4,%5,%6,%7}, {%8,%9}, {%0,%1,%2,%3};\n"
        : "+f"(d[0]), "+f"(d[1]), "+f"(d[2]), "+f"(d[3])
        : "r"(a[0]), "r"(a[1]), "r"(a[2]), "r"(a[3]),
          "r"(b[0]), "r"(b[1]));
}
__device__ __forceinline__ uint32_t smem_u32(const void* p) {
    uint32_t a;
    asm("{ .reg .u64 t; cvta.to.shared.u64 t, %1; cvt.u32.u64 %0, t; }" : "=r"(a) : "l"(p));
    return a;
}
#define CP_ASYNC16(dst_u32, src_ptr) \
    asm volatile("cp.async.ca.shared.global [%0], [%1], 16;\n" \
        :: "r"(dst_u32), "l"(__cvta_generic_to_global(src_ptr)) : "memory")
#define CP_COMMIT() asm volatile("cp.async.commit_group;\n" ::: "memory")
#define CP_WAIT0()  asm volatile("cp.async.wait_group 0;\n" ::: "memory")
#define CP_WAIT1()  asm volatile("cp.async.wait_group 1;\n" ::: "memory")

// ---------------- weight pack ----------------
__global__ void pack_qkv_kernel(const float* __restrict__ Wq,
                                const float* __restrict__ Wk,
                                const float* __restrict__ Wv) {
    int idx = blockIdx.x * blockDim.x + threadIdx.x;
    if (idx >= C_ * 3 * C_) return;
    int c   = idx / (3 * C_);
    int rem = idx - c * (3 * C_);
    int s   = rem >> 10;
    int r2  = rem & 1023;
    int h   = r2 >> 6;
    int d   = r2 & 63;
    const float* W = (s == 0) ? Wq : ((s == 1) ? Wk : Wv);
    g_Wqkv[idx] = W[(h * C_ + c) * HD_ + d];
}

// ============ tf32 mma.sync GEMM: 128x128 CTA tile, BK=32, 8 warps ============
constexpr int EPI_QKV       = 0;
constexpr int EPI_BIAS_RELU = 1;
constexpr int EPI_BIAS_RES  = 2;

#define BM 128
#define BN 128
#define BK 32
#define AS_STRIDE 36
#define BS_STRIDE 136

template <int EPI>
__global__ __launch_bounds__(256, 1)
void gemm_tc(const float* __restrict__ A, const float* __restrict__ Bmat,
             const float* __restrict__ bias, const float* __restrict__ res,
             float* __restrict__ Cout, int M, int N, int K) {
    __shared__ __align__(16) uint32_t As[BM][AS_STRIDE];
    __shared__ __align__(16) uint32_t Bs[BK][BS_STRIDE];

    const int tid = threadIdx.x;
    const int wid = tid >> 5;
    const int lane = tid & 31;
    const int g  = lane >> 2;
    const int tg = lane & 3;
    const int wm = (wid >> 2) * 64;
    const int wn = (wid & 3) * 32;
    const int bm = blockIdx.y * BM;
    const int bn = blockIdx.x * BN;

    float acc[4][4][4];
#pragma unroll
    for (int mi = 0; mi < 4; mi++)
#pragma unroll
        for (int ni = 0; ni < 4; ni++)
#pragma unroll
            for (int j = 0; j < 4; j++) acc[mi][ni][j] = 0.f;

    const int KT = K / BK;

    float4 aR[4], bR[4];
    {
        const float* Ag = A + (size_t)bm * K;
        const float* Bg = Bmat + bn;
#pragma unroll
        for (int i = 0; i < 4; i++) {
            int f = i * 256 + tid;
            int r = f >> 3, c = f & 7;
            aR[i] = *(const float4*)(Ag + (size_t)r * K + c * 4);
            int k = f >> 5, n4 = f & 31;
            bR[i] = *(const float4*)(Bg + (size_t)k * N + n4 * 4);
        }
    }

    for (int kt = 0; kt < KT; ++kt) {
#pragma unroll
        for (int i = 0; i < 4; i++) {
            int f = i * 256 + tid;
            int r = f >> 3, c = f & 7;
            uint4 t;
            t.x = f2tf32(aR[i].x); t.y = f2tf32(aR[i].y);
            t.z = f2tf32(aR[i].z); t.w = f2tf32(aR[i].w);
            *(uint4*)&As[r][c * 4] = t;
            int k = f >> 5, n4 = f & 31;
            uint4 u;
            u.x = f2tf32(bR[i].x); u.y = f2tf32(bR[i].y);
            u.z = f2tf32(bR[i].z); u.w = f2tf32(bR[i].w);
            *(uint4*)&Bs[k][n4 * 4] = u;
        }
        __syncthreads();

        if (kt + 1 < KT) {
            const int k0 = (kt + 1) * BK;
            const float* Ag = A + (size_t)bm * K + k0;
            const float* Bg = Bmat + (size_t)k0 * N + bn;
#pragma unroll
            for (int i = 0; i < 4; i++) {
                int f = i * 256 + tid;
                int r = f >> 3, c = f & 7;
                aR[i] = *(const float4*)(Ag + (size_t)r * K + c * 4);
                int k = f >> 5, n4 = f & 31;
                bR[i] = *(const float4*)(Bg + (size_t)k * N + n4 * 4);
            }
        }

#pragma unroll
        for (int kk8 = 0; kk8 < 4; kk8++) {
            const int kk = kk8 * 8;
            uint32_t af[4][4], bf[4][2];
#pragma unroll
            for (int mi = 0; mi < 4; mi++) {
                int m0 = wm + mi * 16 + g;
                af[mi][0] = As[m0][kk + tg];
                af[mi][1] = As[m0 + 8][kk + tg];
                af[mi][2] = As[m0][kk + tg + 4];
                af[mi][3] = As[m0 + 8][kk + tg + 4];
            }
#pragma unroll
            for (int ni = 0; ni < 4; ni++) {
                int n0 = wn + ni * 8 + g;
                bf[ni][0] = Bs[kk + tg][n0];
                bf[ni][1] = Bs[kk + tg + 4][n0];
            }
#pragma unroll
            for (int mi = 0; mi < 4; mi++)
#pragma unroll
                for (int ni = 0; ni < 4; ni++)
                    mma_tf32(acc[mi][ni], af[mi], bf[ni]);
        }
        __syncthreads();
    }

#pragma unroll
    for (int mi = 0; mi < 4; mi++) {
#pragma unroll
        for (int ni = 0; ni < 4; ni++) {
#pragma unroll
            for (int half = 0; half < 2; half++) {
                int row = bm + wm + mi * 16 + g + half * 8;
                int col = bn + wn + ni * 8 + tg * 2;
                float v0 = acc[mi][ni][half * 2 + 0];
                float v1 = acc[mi][ni][half * 2 + 1];
                if (EPI == EPI_QKV) {
                    int s  = col >> 10;
                    int h  = (col >> 6) & (H_ - 1);
                    int d0 = col & 63;
                    int bb = row >> 11;
                    int t  = row & 2047;
                    if (s == 0) {
                        __half2* dst = (__half2*)(g_qh + (((size_t)(bb * H_ + h) * T_) + t) * HD_ + d0);
                        *dst = __floats2half2_rn(v0 * 0.125f, v1 * 0.125f);
                    } else if (s == 1) {
                        __half2* dst = (__half2*)(g_kh + (((size_t)(bb * H_ + h) * T_) + t) * HD_ + d0);
                        *dst = __floats2half2_rn(v0, v1);
                    } else {
                        __half* base = g_vTh + ((size_t)(bb * H_ + h) * HD_ + d0) * T_ + t;
                        base[0]  = __float2half_rn(v0);
                        base[T_] = __float2half_rn(v1);
                    }
                } else if (EPI == EPI_BIAS_RELU) {
                    float2 bv = *(const float2*)(bias + col);
                    float2 o = make_float2(fmaxf(v0 + bv.x, 0.f), fmaxf(v1 + bv.y, 0.f));
                    *(float2*)(Cout + (size_t)row * N + col) = o;
                } else {
                    float2 bv = *(const float2*)(bias + col);
                    float2 rv = *(const float2*)(res + (size_t)row * N + col);
                    float2 o = make_float2(v0 + bv.x + rv.x, v1 + bv.y + rv.y);
                    *(float2*)(Cout + (size_t)row * N + col) = o;
                }
            }
        }
    }
}

// ====== fp16 tensor-core causal flash attention with cp.async pipeline ======
// CTA: 128 q-rows, 8 warps (16 rows each), key blocks of 64.
// All SMEM strides = 72 halfs (36 words): frag loads hit bank 4g+tg (conflict-free).
// Layout (halfs): Ps[128][72] (Q stage -> P), then K/V double buffers [64][72] x4.
#define HSW 36                                   // stride in 32-bit words
#define PW_WORDS   (128 * HSW)                   // 4608 words
#define TILE_WORDS (64 * HSW)                    // 2304 words
#define ATTN_SMEM_BYTES ((PW_WORDS + 4 * TILE_WORDS) * 4)   // 55296 B

__global__ __launch_bounds__(256, 1)
void attn_tc_kernel() {
    extern __shared__ __align__(16) char smraw[];
    uint32_t* S32 = (uint32_t*)smraw;
    const uint32_t smb = smem_u32(smraw);

    const int tid  = threadIdx.x;
    const int wid  = tid >> 5;
    const int lane = tid & 31;
    const int g    = lane >> 2;
    const int tg   = lane & 3;
    const int bh   = blockIdx.y;
    const int qi   = gridDim.x - 1 - blockIdx.x;   // heavy tiles first
    const int qr0  = qi * 128;

    const __half* qb  = g_qh  + (size_t)bh * T_ * HD_;
    const __half* kb  = g_kh  + (size_t)bh * T_ * HD_;
    const __half* vtb = g_vTh + (size_t)bh * HD_ * T_;

    // ---- stage Q (already scaled + fp16) into P region ----
    for (int j = tid; j < 1024; j += 256) {        // 128 rows x 8 uint4-of-halfs
        int r  = j >> 3;
        int c8 = j & 7;                            // 8 halfs per chunk
        uint4 v = *(const uint4*)(qb + (size_t)(qr0 + r) * HD_ + c8 * 8);
        *(uint4*)(S32 + r * HSW + c8 * 4) = v;
    }
    __syncthreads();

    // ---- extract Q frags (4 k16-steps x 4 regs) ----
    const int mrow = wid * 16;
    uint32_t qf[4][4];
#pragma unroll
    for (int c = 0; c < 4; c++) {
        qf[c][0] = S32[(mrow + g) * HSW + c * 8 + tg];
        qf[c][1] = S32[(mrow + 8 + g) * HSW + c * 8 + tg];
        qf[c][2] = S32[(mrow + g) * HSW + c * 8 + tg + 4];
        qf[c][3] = S32[(mrow + 8 + g) * HSW + c * 8 + tg + 4];
    }
    __syncthreads();                               // P region now reusable

    float m_s[2] = {-1e30f, -1e30f};
    float l_s[2] = {0.f, 0.f};
    float oacc[8][4];
#pragma unroll
    for (int ni = 0; ni < 8; ni++)
#pragma unroll
        for (int j = 0; j < 4; j++) oacc[ni][j] = 0.f;

    const int nblocks = qr0 / 64 + 2;

    // cp.async issue of tile ib into buffer ib&1
    auto issue = [&](int ib) {
        const int bsel = ib & 1;
        const int kc0  = ib * 64;
        const uint32_t kw = (uint32_t)(PW_WORDS + bsel * 2 * TILE_WORDS);
        const uint32_t vw = kw + TILE_WORDS;
#pragma unroll
        for (int t = 0; t < 2; t++) {
            int j   = tid + t * 256;               // 0..511
            int row = j >> 3;
            int c8  = j & 7;
            CP_ASYNC16(smb + (kw + row * HSW + c8 * 4) * 4,
                       kb + (size_t)(kc0 + row) * HD_ + c8 * 8);
            CP_ASYNC16(smb + (vw + row * HSW + c8 * 4) * 4,
                       vtb + (size_t)row * T_ + kc0 + c8 * 8);
        }
        CP_COMMIT();
    };

    issue(0);

    for (int ib = 0; ib < nblocks; ib++) {
        const int kc0  = ib * 64;
        const int bsel = ib & 1;
        const uint32_t* K32 = S32 + PW_WORDS + bsel * 2 * TILE_WORDS;
        const uint32_t* V32 = K32 + TILE_WORDS;

        if (ib + 1 < nblocks) { issue(ib + 1); CP_WAIT1(); }
        else                  { CP_WAIT0(); }
        __syncthreads();                           // tile ib visible to all

        // ---- S = Q K^T ----
        float sacc[8][4];
#pragma unroll
        for (int ni = 0; ni < 8; ni++)
#pragma unroll
            for (int j = 0; j < 4; j++) sacc[ni][j] = 0.f;
#pragma unroll
        for (int c = 0; c < 4; c++) {
#pragma unroll
            for (int ni = 0; ni < 8; ni++) {
                uint32_t bf[2];
                bf[0] = K32[(ni * 8 + g) * HSW + c * 8 + tg];
                bf[1] = K32[(ni * 8 + g) * HSW + c * 8 + tg + 4];
                mma_f16(sacc[ni], qf[c], bf);
            }
        }

        // ---- causal mask ----
        if (kc0 + 63 > qr0 + mrow) {
#pragma unroll
            for (int ni = 0; ni < 8; ni++) {
#pragma unroll
                for (int j = 0; j < 4; j++) {
                    int row = qr0 + mrow + g + ((j >= 2) ? 8 : 0);
                    int col = kc0 + ni * 8 + tg * 2 + (j & 1);
                    if (col > row) sacc[ni][j] = -1e30f;
                }
            }
        }

        // ---- online softmax; write P as half2 ----
#pragma unroll
        for (int r = 0; r < 2; r++) {
            float mx = m_s[r];
#pragma unroll
            for (int ni = 0; ni < 8; ni++)
                mx = fmaxf(mx, fmaxf(sacc[ni][r * 2], sacc[ni][r * 2 + 1]));
            mx = fmaxf(mx, __shfl_xor_sync(0xFFFFFFFFu, mx, 1));
            mx = fmaxf(mx, __shfl_xor_sync(0xFFFFFFFFu, mx, 2));
            float alpha = __expf(m_s[r] - mx);
            m_s[r] = mx;
            float sum = 0.f;
            const int prow = mrow + r * 8 + g;
#pragma unroll
            for (int ni = 0; ni < 8; ni++) {
                float p0 = __expf(sacc[ni][r * 2]     - mx);
                float p1 = __expf(sacc[ni][r * 2 + 1] - mx);
                sum += p0 + p1;
                S32[prow * HSW + ni * 4 + tg] = h22u(__floats2half2_rn(p0, p1));
            }
            sum += __shfl_xor_sync(0xFFFFFFFFu, sum, 1);
            sum += __shfl_xor_sync(0xFFFFFFFFu, sum, 2);
            l_s[r] = l_s[r] * alpha + sum;
#pragma unroll
            for (int ni = 0; ni < 8; ni++) {
                oacc[ni][r * 2]     *= alpha;
                oacc[ni][r * 2 + 1] *= alpha;
            }
        }
        __syncwarp();                              // P rows are warp-private

        // ---- O += P V  (V transposed: B[k=key][n=d] = Vt[d][key]) ----
#pragma unroll
        for (int c = 0; c < 4; c++) {
            uint32_t af[4];
            af[0] = S32[(mrow + g) * HSW + c * 8 + tg];
            af[1] = S32[(mrow + 8 + g) * HSW + c * 8 + tg];
            af[2] = S32[(mrow + g) * HSW + c * 8 + tg + 4];
            af[3] = S32[(mrow + 8 + g) * HSW + c * 8 + tg + 4];
#pragma unroll
            for (int ni = 0; ni < 8; ni++) {
                uint32_t bf[2];
                bf[0] = V32[(ni * 8 + g) * HSW + c * 8 + tg];
                bf[1] = V32[(ni * 8 + g) * HSW + c * 8 + tg + 4];
                mma_f16(oacc[ni], af, bf);
            }
        }
        __syncthreads();                           // done with tile before overwrite
    }

    // ---- epilogue: normalize, store concat layout (fp32) ----
    const int b = bh >> 4;
    const int h = bh & 15;
#pragma unroll
    for (int r = 0; r < 2; r++) {
        float inv = 1.f / l_s[r];
        int t = qr0 + mrow + g + r * 8;
        float* dst = g_attn + ((size_t)(b * T_ + t)) * C_ + h * HD_;
#pragma unroll
        for (int ni = 0; ni < 8; ni++) {
            float2 o;
            o.x = oacc[ni][r * 2]     * inv;
            o.y = oacc[ni][r * 2 + 1] * inv;
            *(float2*)(dst + ni * 8 + tg * 2) = o;
        }
    }
}

// ---------------- LayerNorm over C=1024, 1 row per block ----------------
__global__ __launch_bounds__(256)
void ln_kernel(const float* __restrict__ x, const float* __restrict__ g,
               const float* __restrict__ beta, float* __restrict__ y) {
    const int row = blockIdx.x;
    const int tid = threadIdx.x;
    const float* xr = x + (size_t)row * C_;

    float4 v = *(const float4*)(xr + tid * 4);
    float s  = v.x + v.y + v.z + v.w;
    float s2 = v.x * v.x + v.y * v.y + v.z * v.z + v.w * v.w;
#pragma unroll
    for (int o = 16; o > 0; o >>= 1) {
        s  += __shfl_xor_sync(0xFFFFFFFFu, s, o);
        s2 += __shfl_xor_sync(0xFFFFFFFFu, s2, o);
    }
    __shared__ float sh[16];
    __shared__ float mean_sh, istd_sh;
    int w = tid >> 5, l = tid & 31;
    if (l == 0) { sh[w] = s; sh[w + 8] = s2; }
    __syncthreads();
    if (tid == 0) {
        float ts = 0.f, ts2 = 0.f;
#pragma unroll
        for (int i = 0; i < 8; i++) { ts += sh[i]; ts2 += sh[i + 8]; }
        float mean = ts * (1.f / C_);
        float var  = ts2 * (1.f / C_) - mean * mean;
        mean_sh = mean;
        istd_sh = rsqrtf(var + 1e-5f);
    }
    __syncthreads();
    float mean = mean_sh, istd = istd_sh;
    float4 gv = *(const float4*)(g + tid * 4);
    float4 bv = *(const float4*)(beta + tid * 4);
    float4 out;
    out.x = (v.x - mean) * istd * gv.x + bv.x;
    out.y = (v.y - mean) * istd * gv.y + bv.y;
    out.z = (v.z - mean) * istd * gv.z + bv.z;
    out.w = (v.w - mean) * istd * gv.w + bv.w;
    *(float4*)(y + (size_t)row * C_ + tid * 4) = out;
}

// ---------------- launch ----------------
extern "C" void kernel_launch(void* const* d_in, const int* in_sizes, int n_in,
                              void* d_out, int out_size) {
    (void)in_sizes; (void)n_in; (void)out_size;
    const float* x   = (const float*)d_in[0];
    const float* Wq  = (const float*)d_in[1];
    const float* Wk  = (const float*)d_in[2];
    const float* Wv  = (const float*)d_in[3];
    const float* Wp  = (const float*)d_in[4];
    const float* bp  = (const float*)d_in[5];
    const float* W1  = (const float*)d_in[6];
    const float* b1  = (const float*)d_in[7];
    const float* W2  = (const float*)d_in[8];
    const float* b2  = (const float*)d_in[9];
    const float* g1  = (const float*)d_in[10];
    const float* be1 = (const float*)d_in[11];
    const float* g2  = (const float*)d_in[12];
    const float* be2 = (const float*)d_in[13];

    void *p_wqkv_, *p_attn_, *p_h1_, *p_x1_, *p_ff_, *p_h2_;
    cudaGetSymbolAddress(&p_wqkv_, g_Wqkv);
    cudaGetSymbolAddress(&p_attn_, g_attn);
    cudaGetSymbolAddress(&p_h1_,   g_h1);
    cudaGetSymbolAddress(&p_x1_,   g_x1);
    cudaGetSymbolAddress(&p_ff_,   g_ff);
    cudaGetSymbolAddress(&p_h2_,   g_h2);
    float* p_wqkv = (float*)p_wqkv_;
    float* p_attn = (float*)p_attn_;
    float* p_h1   = (float*)p_h1_;
    float* p_x1   = (float*)p_x1_;
    float* p_ff   = (float*)p_ff_;
    float* p_h2   = (float*)p_h2_;

    cudaFuncSetAttribute(attn_tc_kernel,
                         cudaFuncAttributeMaxDynamicSharedMemorySize, ATTN_SMEM_BYTES);

    // 1. pack qkv weights -> [C, 3C]
    pack_qkv_kernel<<<(C_ * 3 * C_ + 255) / 256, 256>>>(Wq, Wk, Wv);
    // 2. QKV projection (tf32 TC), epilogue converts to fp16 (+V transpose)
    gemm_tc<EPI_QKV><<<dim3(3 * C_ / BN, M_ / BM), 256>>>(
        x, p_wqkv, nullptr, nullptr, nullptr, M_, 3 * C_, C_);
    // 3. causal attention (fp16 TC + cp.async) -> concat layout
    attn_tc_kernel<<<dim3(T_ / 128, B_ * H_), 256, ATTN_SMEM_BYTES>>>();
    // 4. out proj + bias + residual
    gemm_tc<EPI_BIAS_RES><<<dim3(C_ / BN, M_ / BM), 256>>>(
        p_attn, Wp, bp, x, p_h1, M_, C_, C_);
    // 5. LN1
    ln_kernel<<<M_, 256>>>(p_h1, g1, be1, p_x1);
    // 6. FFN up + relu
    gemm_tc<EPI_BIAS_RELU><<<dim3(FF_ / BN, M_ / BM), 256>>>(
        p_x1, W1, b1, nullptr, p_ff, M_, FF_, C_);
    // 7. FFN down + bias + residual
    gemm_tc<EPI_BIAS_RES><<<dim3(C_ / BN, M_ / BM), 256>>>(
        p_ff, W2, b2, p_x1, p_h2, M_, C_, FF_);
    // 8. LN2 -> d_out
    ln_kernel<<<M_, 256>>>(p_h2, g2, be2, (float*)d_out);
}

// round 9
// speedup vs baseline: 3.7753x; 1.0133x over previous
#include <cuda_runtime.h>
#include <cuda_fp16.h>
#include <cstdint>
#include <cmath>

#define B_  2
#define T_  2048
#define C_  1024
#define H_  16
#define HD_ 64
#define M_  (B_ * T_)     // 4096 rows
#define FF_ (4 * C_)      // 4096

// ---------------- scratch (static device allocations; allowed) ----------------
__device__ float  g_Wqkv[C_ * 3 * C_];           // packed [C, 3C] qkv weight
__device__ __half g_qh[B_ * H_ * T_ * HD_];      // [b,h][t][d], pre-scaled 0.125
__device__ __half g_kh[B_ * H_ * T_ * HD_];      // [b,h][t][d]
__device__ __half g_vTh[B_ * H_ * HD_ * T_];     // [b,h][d][t]  (transposed!)
__device__ float  g_attn[M_ * C_];               // attention out, concat layout
__device__ float  g_h1[M_ * C_];
__device__ float  g_x1[M_ * C_];
__device__ float  g_ff[M_ * FF_];
__device__ float  g_h2[M_ * C_];

// ---------------- helpers ----------------
__device__ __forceinline__ uint32_t f2tf32(float f) {
    uint32_t r;
    asm("cvt.rna.tf32.f32 %0, %1;" : "=r"(r) : "f"(f));
    return r;
}
__device__ __forceinline__ uint32_t h22u(__half2 h) {
    __half2_raw hr = *reinterpret_cast<__half2_raw*>(&h);
    return (uint32_t)hr.x | ((uint32_t)hr.y << 16);
}
__device__ __forceinline__ void mma_tf32(float* d, const uint32_t* a, const uint32_t* b) {
    asm volatile(
        "mma.sync.aligned.m16n8k8.row.col.f32.tf32.tf32.f32 "
        "{%0,%1,%2,%3}, {%4,%5,%6,%7}, {%8,%9}, {%0,%1,%2,%3};\n"
        : "+f"(d[0]), "+f"(d[1]), "+f"(d[2]), "+f"(d[3])
        : "r"(a[0]), "r"(a[1]), "r"(a[2]), "r"(a[3]),
          "r"(b[0]), "r"(b[1]));
}
__device__ __forceinline__ void mma_f16(float* d, const uint32_t* a, const uint32_t* b) {
    asm volatile(
        "mma.sync.aligned.m16n8k16.row.col.f32.f16.f16.f32 "
        "{%0,%1,%2,%3}, {%4,%5,%6,%7}, {%8,%9}, {%0,%1,%2,%3};\n"
        : "+f"(d[0]), "+f"(d[1]), "+f"(d[2]), "+f"(d[3])
        : "r"(a[0]), "r"(a[1]), "r"(a[2]), "r"(a[3]),
          "r"(b[0]), "r"(b[1]));
}
__device__ __forceinline__ uint32_t smem_u32(const void* p) {
    uint32_t a;
    asm("{ .reg .u64 t; cvta.to.shared.u64 t, %1; cvt.u32.u64 %0, t; }" : "=r"(a) : "l"(p));
    return a;
}
#define LDMATRIX_X4(r0, r1, r2, r3, addr) \
    asm volatile("ldmatrix.sync.aligned.m8n8.x4.shared.b16 {%0,%1,%2,%3}, [%4];" \
        : "=r"(r0), "=r"(r1), "=r"(r2), "=r"(r3) : "r"(addr))
#define CP_ASYNC16(dst_u32, src_ptr) \
    asm volatile("cp.async.ca.shared.global [%0], [%1], 16;\n" \
        :: "r"(dst_u32), "l"(__cvta_generic_to_global(src_ptr)) : "memory")
#define CP_COMMIT() asm volatile("cp.async.commit_group;\n" ::: "memory")
#define CP_WAIT0()  asm volatile("cp.async.wait_group 0;\n" ::: "memory")
#define CP_WAIT1()  asm volatile("cp.async.wait_group 1;\n" ::: "memory")

// ---------------- weight pack ----------------
__global__ void pack_qkv_kernel(const float* __restrict__ Wq,
                                const float* __restrict__ Wk,
                                const float* __restrict__ Wv) {
    int idx = blockIdx.x * blockDim.x + threadIdx.x;
    if (idx >= C_ * 3 * C_) return;
    int c   = idx / (3 * C_);
    int rem = idx - c * (3 * C_);
    int s   = rem >> 10;
    int r2  = rem & 1023;
    int h   = r2 >> 6;
    int d   = r2 & 63;
    const float* W = (s == 0) ? Wq : ((s == 1) ? Wk : Wv);
    g_Wqkv[idx] = W[(h * C_ + c) * HD_ + d];
}

// ============ tf32 mma.sync GEMM: 128x128 CTA tile, BK=32, 8 warps ============
constexpr int EPI_QKV       = 0;
constexpr int EPI_BIAS_RELU = 1;
constexpr int EPI_BIAS_RES  = 2;

#define BM 128
#define BN 128
#define BK 32
#define AS_STRIDE 36
#define BS_STRIDE 136

template <int EPI>
__global__ __launch_bounds__(256, 1)
void gemm_tc(const float* __restrict__ A, const float* __restrict__ Bmat,
             const float* __restrict__ bias, const float* __restrict__ res,
             float* __restrict__ Cout, int M, int N, int K) {
    __shared__ __align__(16) uint32_t As[BM][AS_STRIDE];
    __shared__ __align__(16) uint32_t Bs[BK][BS_STRIDE];

    const int tid = threadIdx.x;
    const int wid = tid >> 5;
    const int lane = tid & 31;
    const int g  = lane >> 2;
    const int tg = lane & 3;
    const int wm = (wid >> 2) * 64;
    const int wn = (wid & 3) * 32;
    const int bm = blockIdx.y * BM;
    const int bn = blockIdx.x * BN;

    float acc[4][4][4];
#pragma unroll
    for (int mi = 0; mi < 4; mi++)
#pragma unroll
        for (int ni = 0; ni < 4; ni++)
#pragma unroll
            for (int j = 0; j < 4; j++) acc[mi][ni][j] = 0.f;

    const int KT = K / BK;

    float4 aR[4], bR[4];
    {
        const float* Ag = A + (size_t)bm * K;
        const float* Bg = Bmat + bn;
#pragma unroll
        for (int i = 0; i < 4; i++) {
            int f = i * 256 + tid;
            int r = f >> 3, c = f & 7;
            aR[i] = *(const float4*)(Ag + (size_t)r * K + c * 4);
            int k = f >> 5, n4 = f & 31;
            bR[i] = *(const float4*)(Bg + (size_t)k * N + n4 * 4);
        }
    }

    for (int kt = 0; kt < KT; ++kt) {
#pragma unroll
        for (int i = 0; i < 4; i++) {
            int f = i * 256 + tid;
            int r = f >> 3, c = f & 7;
            uint4 t;
            t.x = f2tf32(aR[i].x); t.y = f2tf32(aR[i].y);
            t.z = f2tf32(aR[i].z); t.w = f2tf32(aR[i].w);
            *(uint4*)&As[r][c * 4] = t;
            int k = f >> 5, n4 = f & 31;
            uint4 u;
            u.x = f2tf32(bR[i].x); u.y = f2tf32(bR[i].y);
            u.z = f2tf32(bR[i].z); u.w = f2tf32(bR[i].w);
            *(uint4*)&Bs[k][n4 * 4] = u;
        }
        __syncthreads();

        if (kt + 1 < KT) {
            const int k0 = (kt + 1) * BK;
            const float* Ag = A + (size_t)bm * K + k0;
            const float* Bg = Bmat + (size_t)k0 * N + bn;
#pragma unroll
            for (int i = 0; i < 4; i++) {
                int f = i * 256 + tid;
                int r = f >> 3, c = f & 7;
                aR[i] = *(const float4*)(Ag + (size_t)r * K + c * 4);
                int k = f >> 5, n4 = f & 31;
                bR[i] = *(const float4*)(Bg + (size_t)k * N + n4 * 4);
            }
        }

#pragma unroll
        for (int kk8 = 0; kk8 < 4; kk8++) {
            const int kk = kk8 * 8;
            uint32_t af[4][4], bf[4][2];
#pragma unroll
            for (int mi = 0; mi < 4; mi++) {
                int m0 = wm + mi * 16 + g;
                af[mi][0] = As[m0][kk + tg];
                af[mi][1] = As[m0 + 8][kk + tg];
                af[mi][2] = As[m0][kk + tg + 4];
                af[mi][3] = As[m0 + 8][kk + tg + 4];
            }
#pragma unroll
            for (int ni = 0; ni < 4; ni++) {
                int n0 = wn + ni * 8 + g;
                bf[ni][0] = Bs[kk + tg][n0];
                bf[ni][1] = Bs[kk + tg + 4][n0];
            }
#pragma unroll
            for (int mi = 0; mi < 4; mi++)
#pragma unroll
                for (int ni = 0; ni < 4; ni++)
                    mma_tf32(acc[mi][ni], af[mi], bf[ni]);
        }
        __syncthreads();
    }

#pragma unroll
    for (int mi = 0; mi < 4; mi++) {
#pragma unroll
        for (int ni = 0; ni < 4; ni++) {
#pragma unroll
            for (int half = 0; half < 2; half++) {
                int row = bm + wm + mi * 16 + g + half * 8;
                int col = bn + wn + ni * 8 + tg * 2;
                float v0 = acc[mi][ni][half * 2 + 0];
                float v1 = acc[mi][ni][half * 2 + 1];
                if (EPI == EPI_QKV) {
                    int s  = col >> 10;
                    int h  = (col >> 6) & (H_ - 1);
                    int d0 = col & 63;
                    int bb = row >> 11;
                    int t  = row & 2047;
                    if (s == 0) {
                        __half2* dst = (__half2*)(g_qh + (((size_t)(bb * H_ + h) * T_) + t) * HD_ + d0);
                        *dst = __floats2half2_rn(v0 * 0.125f, v1 * 0.125f);
                    } else if (s == 1) {
                        __half2* dst = (__half2*)(g_kh + (((size_t)(bb * H_ + h) * T_) + t) * HD_ + d0);
                        *dst = __floats2half2_rn(v0, v1);
                    } else {
                        __half* base = g_vTh + ((size_t)(bb * H_ + h) * HD_ + d0) * T_ + t;
                        base[0]  = __float2half_rn(v0);
                        base[T_] = __float2half_rn(v1);
                    }
                } else if (EPI == EPI_BIAS_RELU) {
                    float2 bv = *(const float2*)(bias + col);
                    float2 o = make_float2(fmaxf(v0 + bv.x, 0.f), fmaxf(v1 + bv.y, 0.f));
                    *(float2*)(Cout + (size_t)row * N + col) = o;
                } else {
                    float2 bv = *(const float2*)(bias + col);
                    float2 rv = *(const float2*)(res + (size_t)row * N + col);
                    float2 o = make_float2(v0 + bv.x + rv.x, v1 + bv.y + rv.y);
                    *(float2*)(Cout + (size_t)row * N + col) = o;
                }
            }
        }
    }
}

// ====== fp16 TC causal flash attention: P-in-registers + ldmatrix + 2 CTA/SM ======
// CTA: 128 q-rows, 8 warps (16 rows each), key blocks of 64.
// SMEM: only K/V double buffers, 4 x [64][72 halfs] = 36864 B. Q staged through
// buffers 0+1 before the pipeline starts. Stride 36 words: conflict-free.
#define HSW 36                                   // row stride in 32-bit words
#define TILE_WORDS (64 * HSW)                    // 2304 words
#define ATTN_SMEM_BYTES (4 * TILE_WORDS * 4)     // 36864 B

__global__ __launch_bounds__(256, 2)
void attn_tc_kernel() {
    extern __shared__ __align__(16) char smraw[];
    uint32_t* S32 = (uint32_t*)smraw;
    const uint32_t smb = smem_u32(smraw);

    const int tid  = threadIdx.x;
    const int wid  = tid >> 5;
    const int lane = tid & 31;
    const int g    = lane >> 2;
    const int tg   = lane & 3;
    const int bh   = blockIdx.y;
    const int qi   = gridDim.x - 1 - blockIdx.x;   // heavy tiles first
    const int qr0  = qi * 128;

    const __half* qb  = g_qh  + (size_t)bh * T_ * HD_;
    const __half* kb  = g_kh  + (size_t)bh * T_ * HD_;
    const __half* vtb = g_vTh + (size_t)bh * HD_ * T_;

    // ---- stage Q through the tile-buffer region, extract frags, then free it ----
    for (int j = tid; j < 1024; j += 256) {        // 128 rows x 8 uint4-of-halfs
        int r  = j >> 3;
        int c8 = j & 7;
        uint4 v = *(const uint4*)(qb + (size_t)(qr0 + r) * HD_ + c8 * 8);
        *(uint4*)(S32 + r * HSW + c8 * 4) = v;
    }
    __syncthreads();
    const int mrow = wid * 16;
    uint32_t qf[4][4];
#pragma unroll
    for (int c = 0; c < 4; c++) {
        qf[c][0] = S32[(mrow + g) * HSW + c * 8 + tg];
        qf[c][1] = S32[(mrow + 8 + g) * HSW + c * 8 + tg];
        qf[c][2] = S32[(mrow + g) * HSW + c * 8 + tg + 4];
        qf[c][3] = S32[(mrow + 8 + g) * HSW + c * 8 + tg + 4];
    }
    __syncthreads();                               // buffers now free for K/V

    // per-lane ldmatrix base (same formula for K and V tiles):
    // tile sel t = lane>>3: t&2 selects row-block +8, t&1 selects k-half (+4 words)
    const int tsel   = lane >> 3;
    const int rowi   = lane & 7;
    const uint32_t lm_common =
        (uint32_t)(((tsel & 2) ? 8 : 0) + rowi) * HSW + (uint32_t)((tsel & 1) * 4);

    float m_s[2] = {-1e30f, -1e30f};
    float l_s[2] = {0.f, 0.f};
    float oacc[8][4];
#pragma unroll
    for (int ni = 0; ni < 8; ni++)
#pragma unroll
        for (int j = 0; j < 4; j++) oacc[ni][j] = 0.f;

    const int nblocks = qr0 / 64 + 2;

    auto issue = [&](int ib) {
        const int bsel = ib & 1;
        const int kc0  = ib * 64;
        const uint32_t kw = (uint32_t)(bsel * 2 * TILE_WORDS);
        const uint32_t vw = kw + TILE_WORDS;
#pragma unroll
        for (int t = 0; t < 2; t++) {
            int j   = tid + t * 256;               // 0..511
            int row = j >> 3;
            int c8  = j & 7;
            CP_ASYNC16(smb + (kw + row * HSW + c8 * 4) * 4,
                       kb + (size_t)(kc0 + row) * HD_ + c8 * 8);
            CP_ASYNC16(smb + (vw + row * HSW + c8 * 4) * 4,
                       vtb + (size_t)row * T_ + kc0 + c8 * 8);
        }
        CP_COMMIT();
    };

    issue(0);

    for (int ib = 0; ib < nblocks; ib++) {
        const int kc0  = ib * 64;
        const int bsel = ib & 1;
        const uint32_t kbase = smb + ((uint32_t)(bsel * 2 * TILE_WORDS) + lm_common) * 4;
        const uint32_t vbase = kbase + TILE_WORDS * 4;

        if (ib + 1 < nblocks) { issue(ib + 1); CP_WAIT1(); }
        else                  { CP_WAIT0(); }
        __syncthreads();                           // tile ib visible to all

        // ---- S = Q K^T : ldmatrix.x4 delivers b-frags for ni=2p, 2p+1 ----
        float sacc[8][4];
#pragma unroll
        for (int ni = 0; ni < 8; ni++)
#pragma unroll
            for (int j = 0; j < 4; j++) sacc[ni][j] = 0.f;
#pragma unroll
        for (int c = 0; c < 4; c++) {
#pragma unroll
            for (int p = 0; p < 4; p++) {
                uint32_t b0, b1, b2, b3;
                LDMATRIX_X4(b0, b1, b2, b3,
                            kbase + (uint32_t)(p * 16 * HSW + c * 8) * 4);
                uint32_t bf0[2] = {b0, b1};
                uint32_t bf1[2] = {b2, b3};
                mma_f16(sacc[2 * p],     qf[c], bf0);
                mma_f16(sacc[2 * p + 1], qf[c], bf1);
            }
        }

        // ---- causal mask (near diagonal only) ----
        if (kc0 + 63 > qr0 + mrow) {
#pragma unroll
            for (int ni = 0; ni < 8; ni++) {
#pragma unroll
                for (int j = 0; j < 4; j++) {
                    int row = qr0 + mrow + g + ((j >= 2) ? 8 : 0);
                    int col = kc0 + ni * 8 + tg * 2 + (j & 1);
                    if (col > row) sacc[ni][j] = -1e30f;
                }
            }
        }

        // ---- online softmax; P stays in registers as half2 A-frags ----
        uint32_t pf[8][2];                         // [ni][r]
#pragma unroll
        for (int r = 0; r < 2; r++) {
            float mx = m_s[r];
#pragma unroll
            for (int ni = 0; ni < 8; ni++)
                mx = fmaxf(mx, fmaxf(sacc[ni][r * 2], sacc[ni][r * 2 + 1]));
            mx = fmaxf(mx, __shfl_xor_sync(0xFFFFFFFFu, mx, 1));
            mx = fmaxf(mx, __shfl_xor_sync(0xFFFFFFFFu, mx, 2));
            float alpha = __expf(m_s[r] - mx);
            m_s[r] = mx;
            float sum = 0.f;
#pragma unroll
            for (int ni = 0; ni < 8; ni++) {
                float p0 = __expf(sacc[ni][r * 2]     - mx);
                float p1 = __expf(sacc[ni][r * 2 + 1] - mx);
                sum += p0 + p1;
                pf[ni][r] = h22u(__floats2half2_rn(p0, p1));
            }
            sum += __shfl_xor_sync(0xFFFFFFFFu, sum, 1);
            sum += __shfl_xor_sync(0xFFFFFFFFu, sum, 2);
            l_s[r] = l_s[r] * alpha + sum;
#pragma unroll
            for (int ni = 0; ni < 8; ni++) {
                oacc[ni][r * 2]     *= alpha;
                oacc[ni][r * 2 + 1] *= alpha;
            }
        }

        // ---- O += P V : A-frags from pf (C-frag of S == A-frag of PV) ----
#pragma unroll
        for (int c = 0; c < 4; c++) {
            uint32_t af[4] = {pf[2 * c][0], pf[2 * c][1],
                              pf[2 * c + 1][0], pf[2 * c + 1][1]};
#pragma unroll
            for (int p = 0; p < 4; p++) {
                uint32_t b0, b1, b2, b3;
                LDMATRIX_X4(b0, b1, b2, b3,
                            vbase + (uint32_t)(p * 16 * HSW + c * 8) * 4);
                uint32_t bf0[2] = {b0, b1};
                uint32_t bf1[2] = {b2, b3};
                mma_f16(oacc[2 * p],     af, bf0);
                mma_f16(oacc[2 * p + 1], af, bf1);
            }
        }
        __syncthreads();                           // done with tile before overwrite
    }

    // ---- epilogue: normalize, store concat layout (fp32) ----
    const int b = bh >> 4;
    const int h = bh & 15;
#pragma unroll
    for (int r = 0; r < 2; r++) {
        float inv = 1.f / l_s[r];
        int t = qr0 + mrow + g + r * 8;
        float* dst = g_attn + ((size_t)(b * T_ + t)) * C_ + h * HD_;
#pragma unroll
        for (int ni = 0; ni < 8; ni++) {
            float2 o;
            o.x = oacc[ni][r * 2]     * inv;
            o.y = oacc[ni][r * 2 + 1] * inv;
            *(float2*)(dst + ni * 8 + tg * 2) = o;
        }
    }
}

// ---------------- LayerNorm over C=1024, 1 row per block ----------------
__global__ __launch_bounds__(256)
void ln_kernel(const float* __restrict__ x, const float* __restrict__ g,
               const float* __restrict__ beta, float* __restrict__ y) {
    const int row = blockIdx.x;
    const int tid = threadIdx.x;
    const float* xr = x + (size_t)row * C_;

    float4 v = *(const float4*)(xr + tid * 4);
    float s  = v.x + v.y + v.z + v.w;
    float s2 = v.x * v.x + v.y * v.y + v.z * v.z + v.w * v.w;
#pragma unroll
    for (int o = 16; o > 0; o >>= 1) {
        s  += __shfl_xor_sync(0xFFFFFFFFu, s, o);
        s2 += __shfl_xor_sync(0xFFFFFFFFu, s2, o);
    }
    __shared__ float sh[16];
    __shared__ float mean_sh, istd_sh;
    int w = tid >> 5, l = tid & 31;
    if (l == 0) { sh[w] = s; sh[w + 8] = s2; }
    __syncthreads();
    if (tid == 0) {
        float ts = 0.f, ts2 = 0.f;
#pragma unroll
        for (int i = 0; i < 8; i++) { ts += sh[i]; ts2 += sh[i + 8]; }
        float mean = ts * (1.f / C_);
        float var  = ts2 * (1.f / C_) - mean * mean;
        mean_sh = mean;
        istd_sh = rsqrtf(var + 1e-5f);
    }
    __syncthreads();
    float mean = mean_sh, istd = istd_sh;
    float4 gv = *(const float4*)(g + tid * 4);
    float4 bv = *(const float4*)(beta + tid * 4);
    float4 out;
    out.x = (v.x - mean) * istd * gv.x + bv.x;
    out.y = (v.y - mean) * istd * gv.y + bv.y;
    out.z = (v.z - mean) * istd * gv.z + bv.z;
    out.w = (v.w - mean) * istd * gv.w + bv.w;
    *(float4*)(y + (size_t)row * C_ + tid * 4) = out;
}

// ---------------- launch ----------------
extern "C" void kernel_launch(void* const* d_in, const int* in_sizes, int n_in,
                              void* d_out, int out_size) {
    (void)in_sizes; (void)n_in; (void)out_size;
    const float* x   = (const float*)d_in[0];
    const float* Wq  = (const float*)d_in[1];
    const float* Wk  = (const float*)d_in[2];
    const float* Wv  = (const float*)d_in[3];
    const float* Wp  = (const float*)d_in[4];
    const float* bp  = (const float*)d_in[5];
    const float* W1  = (const float*)d_in[6];
    const float* b1  = (const float*)d_in[7];
    const float* W2  = (const float*)d_in[8];
    const float* b2  = (const float*)d_in[9];
    const float* g1  = (const float*)d_in[10];
    const float* be1 = (const float*)d_in[11];
    const float* g2  = (const float*)d_in[12];
    const float* be2 = (const float*)d_in[13];

    void *p_wqkv_, *p_attn_, *p_h1_, *p_x1_, *p_ff_, *p_h2_;
    cudaGetSymbolAddress(&p_wqkv_, g_Wqkv);
    cudaGetSymbolAddress(&p_attn_, g_attn);
    cudaGetSymbolAddress(&p_h1_,   g_h1);
    cudaGetSymbolAddress(&p_x1_,   g_x1);
    cudaGetSymbolAddress(&p_ff_,   g_ff);
    cudaGetSymbolAddress(&p_h2_,   g_h2);
    float* p_wqkv = (float*)p_wqkv_;
    float* p_attn = (float*)p_attn_;
    float* p_h1   = (float*)p_h1_;
    float* p_x1   = (float*)p_x1_;
    float* p_ff   = (float*)p_ff_;
    float* p_h2   = (float*)p_h2_;

    cudaFuncSetAttribute(attn_tc_kernel,
                         cudaFuncAttributeMaxDynamicSharedMemorySize, ATTN_SMEM_BYTES);

    // 1. pack qkv weights -> [C, 3C]
    pack_qkv_kernel<<<(C_ * 3 * C_ + 255) / 256, 256>>>(Wq, Wk, Wv);
    // 2. QKV projection (tf32 TC), epilogue converts to fp16 (+V transpose)
    gemm_tc<EPI_QKV><<<dim3(3 * C_ / BN, M_ / BM), 256>>>(
        x, p_wqkv, nullptr, nullptr, nullptr, M_, 3 * C_, C_);
    // 3. causal attention (fp16 TC, P-in-regs, ldmatrix, 2 CTA/SM)
    attn_tc_kernel<<<dim3(T_ / 128, B_ * H_), 256, ATTN_SMEM_BYTES>>>();
    // 4. out proj + bias + residual
    gemm_tc<EPI_BIAS_RES><<<dim3(C_ / BN, M_ / BM), 256>>>(
        p_attn, Wp, bp, x, p_h1, M_, C_, C_);
    // 5. LN1
    ln_kernel<<<M_, 256>>>(p_h1, g1, be1, p_x1);
    // 6. FFN up + relu
    gemm_tc<EPI_BIAS_RELU><<<dim3(FF_ / BN, M_ / BM), 256>>>(
        p_x1, W1, b1, nullptr, p_ff, M_, FF_, C_);
    // 7. FFN down + bias + residual
    gemm_tc<EPI_BIAS_RES><<<dim3(C_ / BN, M_ / BM), 256>>>(
        p_ff, W2, b2, p_x1, p_h2, M_, C_, FF_);
    // 8. LN2 -> d_out
    ln_kernel<<<M_, 256>>>(p_h2, g2, be2, (float*)d_out);
}

// round 10
// speedup vs baseline: 3.9877x; 1.0563x over previous
#include <cuda_runtime.h>
#include <cuda_fp16.h>
#include <cstdint>
#include <cmath>

#define B_  2
#define T_  2048
#define C_  1024
#define H_  16
#define HD_ 64
#define M_  (B_ * T_)     // 4096 rows
#define FF_ (4 * C_)      // 4096

// ---------------- scratch (static device allocations; allowed) ----------------
__device__ float  g_Wqkv[C_ * 3 * C_];           // packed [C, 3C] qkv weight (tf32 bits)
__device__ float  g_xt[M_ * C_];                 // x converted to tf32 bits
__device__ float  g_Wpt[C_ * C_];                // Wp tf32 bits
__device__ float  g_W1t[C_ * FF_];               // W1 tf32 bits
__device__ float  g_W2t[FF_ * C_];               // W2 tf32 bits
__device__ __half g_qh[B_ * H_ * T_ * HD_];      // [b,h][t][d], pre-scaled 0.125
__device__ __half g_kh[B_ * H_ * T_ * HD_];      // [b,h][t][d]
__device__ __half g_vh[B_ * H_ * T_ * HD_];      // [b,h][t][d] (natural layout)
__device__ float  g_attn[M_ * C_];               // attention out (tf32 bits)
__device__ float  g_h1[M_ * C_];                 // raw f32
__device__ float  g_x1[M_ * C_];                 // LN1 out raw f32
__device__ float  g_x1t[M_ * C_];                // LN1 out tf32 bits
__device__ float  g_ff[M_ * FF_];                // relu(x1 W1 + b1) tf32 bits
__device__ float  g_h2[M_ * C_];                 // raw f32

// ---------------- helpers ----------------
__device__ __forceinline__ uint32_t f2tf32(float f) {
    uint32_t r;
    asm("cvt.rna.tf32.f32 %0, %1;" : "=r"(r) : "f"(f));
    return r;
}
__device__ __forceinline__ uint32_t h22u(__half2 h) {
    __half2_raw hr = *reinterpret_cast<__half2_raw*>(&h);
    return (uint32_t)hr.x | ((uint32_t)hr.y << 16);
}
__device__ __forceinline__ void mma_tf32(float* d, const uint32_t* a, const uint32_t* b) {
    asm volatile(
        "mma.sync.aligned.m16n8k8.row.col.f32.tf32.tf32.f32 "
        "{%0,%1,%2,%3}, {%4,%5,%6,%7}, {%8,%9}, {%0,%1,%2,%3};\n"
        : "+f"(d[0]), "+f"(d[1]), "+f"(d[2]), "+f"(d[3])
        : "r"(a[0]), "r"(a[1]), "r"(a[2]), "r"(a[3]),
          "r"(b[0]), "r"(b[1]));
}
__device__ __forceinline__ void mma_f16(float* d, const uint32_t* a, const uint32_t* b) {
    asm volatile(
        "mma.sync.aligned.m16n8k16.row.col.f32.f16.f16.f32 "
        "{%0,%1,%2,%3}, {%4,%5,%6,%7}, {%8,%9}, {%0,%1,%2,%3};\n"
        : "+f"(d[0]), "+f"(d[1]), "+f"(d[2]), "+f"(d[3])
        : "r"(a[0]), "r"(a[1]), "r"(a[2]), "r"(a[3]),
          "r"(b[0]), "r"(b[1]));
}
__device__ __forceinline__ uint32_t smem_u32(const void* p) {
    uint32_t a;
    asm("{ .reg .u64 t; cvta.to.shared.u64 t, %1; cvt.u32.u64 %0, t; }" : "=r"(a) : "l"(p));
    return a;
}
#define LDMATRIX_X4(r0, r1, r2, r3, addr) \
    asm volatile("ldmatrix.sync.aligned.m8n8.x4.shared.b16 {%0,%1,%2,%3}, [%4];" \
        : "=r"(r0), "=r"(r1), "=r"(r2), "=r"(r3) : "r"(addr))
#define LDMATRIX_X4_TRANS(r0, r1, r2, r3, addr) \
    asm volatile("ldmatrix.sync.aligned.m8n8.x4.trans.shared.b16 {%0,%1,%2,%3}, [%4];" \
        : "=r"(r0), "=r"(r1), "=r"(r2), "=r"(r3) : "r"(addr))
#define CP_ASYNC16(dst_u32, src_ptr) \
    asm volatile("cp.async.ca.shared.global [%0], [%1], 16;\n" \
        :: "r"(dst_u32), "l"(__cvta_generic_to_global(src_ptr)) : "memory")
#define CP_COMMIT() asm volatile("cp.async.commit_group;\n" ::: "memory")
#define CP_WAIT0()  asm volatile("cp.async.wait_group 0;\n" ::: "memory")
#define CP_WAIT1()  asm volatile("cp.async.wait_group 1;\n" ::: "memory")

// ---------------- tf32 convert kernel ----------------
__global__ void cvt_tf32_kernel(const float* __restrict__ in, float* __restrict__ out, int n4) {
    int i = blockIdx.x * blockDim.x + threadIdx.x;
    if (i >= n4) return;
    float4 v = ((const float4*)in)[i];
    uint4 o;
    o.x = f2tf32(v.x); o.y = f2tf32(v.y); o.z = f2tf32(v.z); o.w = f2tf32(v.w);
    ((uint4*)out)[i] = o;
}

// ---------------- weight pack (stores tf32 bits) ----------------
__global__ void pack_qkv_kernel(const float* __restrict__ Wq,
                                const float* __restrict__ Wk,
                                const float* __restrict__ Wv) {
    int idx = blockIdx.x * blockDim.x + threadIdx.x;
    if (idx >= C_ * 3 * C_) return;
    int c   = idx / (3 * C_);
    int rem = idx - c * (3 * C_);
    int s   = rem >> 10;
    int r2  = rem & 1023;
    int h   = r2 >> 6;
    int d   = r2 & 63;
    const float* W = (s == 0) ? Wq : ((s == 1) ? Wk : Wv);
    g_Wqkv[idx] = __uint_as_float(f2tf32(W[(h * C_ + c) * HD_ + d]));
}

// ============ tf32 GEMM v2: cp.async 3-stage pipeline, 2 CTAs/SM ============
// Inputs A, Bmat hold tf32-converted bit patterns (as float).
constexpr int EPI_QKV       = 0;
constexpr int EPI_BIAS_RELU = 1;
constexpr int EPI_BIAS_RES  = 2;

#define BM 128
#define BN 128
#define BK 32
#define ASW 36                      // A tile row stride (words), [m][k]
#define BSW 136                     // B tile row stride (words), [k][n]
#define A_TILE_W (BM * ASW)         // 4608 words
#define B_TILE_W (BK * BSW)         // 4352 words
#define STAGE_W  (A_TILE_W + B_TILE_W)   // 8960 words
#define GEMM_SMEM_BYTES (3 * STAGE_W * 4)   // 107520 B

template <int EPI>
__global__ __launch_bounds__(256, 2)
void gemm_tc(const float* __restrict__ A, const float* __restrict__ Bmat,
             const float* __restrict__ bias, const float* __restrict__ res,
             float* __restrict__ Cout, int M, int N, int K) {
    extern __shared__ __align__(16) char smraw[];
    uint32_t* S32 = (uint32_t*)smraw;
    const uint32_t smb = smem_u32(smraw);

    const int tid = threadIdx.x;
    const int wid = tid >> 5;
    const int lane = tid & 31;
    const int g  = lane >> 2;
    const int tg = lane & 3;
    const int wm = (wid >> 2) * 64;
    const int wn = (wid & 3) * 32;
    const int bm = blockIdx.y * BM;
    const int bn = blockIdx.x * BN;

    float acc[4][4][4];
#pragma unroll
    for (int mi = 0; mi < 4; mi++)
#pragma unroll
        for (int ni = 0; ni < 4; ni++)
#pragma unroll
            for (int j = 0; j < 4; j++) acc[mi][ni][j] = 0.f;

    const int KT = K / BK;

    auto issue = [&](int kt) {
        if (kt < KT) {
            const int k0 = kt * BK;
            const uint32_t base = (uint32_t)((kt % 3) * STAGE_W);
#pragma unroll
            for (int i = 0; i < 4; i++) {           // A: 128 rows x 8 chunks
                int f = i * 256 + tid;
                int r = f >> 3, c = f & 7;
                CP_ASYNC16(smb + (base + r * ASW + c * 4) * 4,
                           A + (size_t)(bm + r) * K + k0 + c * 4);
            }
#pragma unroll
            for (int i = 0; i < 4; i++) {           // B: 32 rows x 32 chunks
                int f = i * 256 + tid;
                int k = f >> 5, n4 = f & 31;
                CP_ASYNC16(smb + (base + A_TILE_W + k * BSW + n4 * 4) * 4,
                           Bmat + (size_t)(k0 + k) * N + bn + n4 * 4);
            }
        }
        CP_COMMIT();   // always commit (possibly-empty group keeps counts aligned)
    };

    issue(0);
    issue(1);

    for (int kt = 0; kt < KT; ++kt) {
        CP_WAIT1();                // tile kt arrived (<=1 outstanding group)
        __syncthreads();           // also: all warps done reading buf[(kt-1)%3]
        issue(kt + 2);             // fills buf[(kt+2)%3] == buf[(kt-1)%3]

        const uint32_t* Abuf = S32 + (kt % 3) * STAGE_W;
        const uint32_t* Bbuf = Abuf + A_TILE_W;

#pragma unroll
        for (int kk8 = 0; kk8 < 4; kk8++) {
            const int kk = kk8 * 8;
            uint32_t af[4][4], bf[4][2];
#pragma unroll
            for (int mi = 0; mi < 4; mi++) {
                int m0 = wm + mi * 16 + g;
                af[mi][0] = Abuf[m0 * ASW + kk + tg];
                af[mi][1] = Abuf[(m0 + 8) * ASW + kk + tg];
                af[mi][2] = Abuf[m0 * ASW + kk + tg + 4];
                af[mi][3] = Abuf[(m0 + 8) * ASW + kk + tg + 4];
            }
#pragma unroll
            for (int ni = 0; ni < 4; ni++) {
                int n0 = wn + ni * 8 + g;
                bf[ni][0] = Bbuf[(kk + tg) * BSW + n0];
                bf[ni][1] = Bbuf[(kk + tg + 4) * BSW + n0];
            }
#pragma unroll
            for (int mi = 0; mi < 4; mi++)
#pragma unroll
                for (int ni = 0; ni < 4; ni++)
                    mma_tf32(acc[mi][ni], af[mi], bf[ni]);
        }
        // no trailing sync: next iter's sync protects buffer reuse
    }

#pragma unroll
    for (int mi = 0; mi < 4; mi++) {
#pragma unroll
        for (int ni = 0; ni < 4; ni++) {
#pragma unroll
            for (int half = 0; half < 2; half++) {
                int row = bm + wm + mi * 16 + g + half * 8;
                int col = bn + wn + ni * 8 + tg * 2;
                float v0 = acc[mi][ni][half * 2 + 0];
                float v1 = acc[mi][ni][half * 2 + 1];
                if (EPI == EPI_QKV) {
                    int s  = col >> 10;
                    int h  = (col >> 6) & (H_ - 1);
                    int d0 = col & 63;
                    int bb = row >> 11;
                    int t  = row & 2047;
                    size_t off = (((size_t)(bb * H_ + h) * T_) + t) * HD_ + d0;
                    if (s == 0) {
                        *(__half2*)(g_qh + off) = __floats2half2_rn(v0 * 0.125f, v1 * 0.125f);
                    } else if (s == 1) {
                        *(__half2*)(g_kh + off) = __floats2half2_rn(v0, v1);
                    } else {
                        *(__half2*)(g_vh + off) = __floats2half2_rn(v0, v1);
                    }
                } else if (EPI == EPI_BIAS_RELU) {
                    float2 bv = *(const float2*)(bias + col);
                    float2 o;
                    o.x = __uint_as_float(f2tf32(fmaxf(v0 + bv.x, 0.f)));
                    o.y = __uint_as_float(f2tf32(fmaxf(v1 + bv.y, 0.f)));
                    *(float2*)(Cout + (size_t)row * N + col) = o;   // tf32 bits
                } else {
                    float2 bv = *(const float2*)(bias + col);
                    float2 rv = *(const float2*)(res + (size_t)row * N + col);
                    float2 o = make_float2(v0 + bv.x + rv.x, v1 + bv.y + rv.y);
                    *(float2*)(Cout + (size_t)row * N + col) = o;   // raw f32
                }
            }
        }
    }
}

// ====== fp16 TC causal flash attention: P-in-regs, ldmatrix(+trans V), 2 CTA/SM ======
#define HSW 36                                   // row stride in 32-bit words
#define TILE_WORDS (64 * HSW)                    // 2304 words
#define ATTN_SMEM_BYTES (4 * TILE_WORDS * 4)     // 36864 B

__global__ __launch_bounds__(256, 2)
void attn_tc_kernel() {
    extern __shared__ __align__(16) char smraw[];
    uint32_t* S32 = (uint32_t*)smraw;
    const uint32_t smb = smem_u32(smraw);

    const int tid  = threadIdx.x;
    const int wid  = tid >> 5;
    const int lane = tid & 31;
    const int g    = lane >> 2;
    const int tg   = lane & 3;
    const int bh   = blockIdx.y;
    const int qi   = gridDim.x - 1 - blockIdx.x;   // heavy tiles first
    const int qr0  = qi * 128;

    const __half* qb = g_qh + (size_t)bh * T_ * HD_;
    const __half* kb = g_kh + (size_t)bh * T_ * HD_;
    const __half* vb = g_vh + (size_t)bh * T_ * HD_;

    // ---- stage Q through the tile-buffer region, extract frags, then free it ----
    for (int j = tid; j < 1024; j += 256) {
        int r  = j >> 3;
        int c8 = j & 7;
        uint4 v = *(const uint4*)(qb + (size_t)(qr0 + r) * HD_ + c8 * 8);
        *(uint4*)(S32 + r * HSW + c8 * 4) = v;
    }
    __syncthreads();
    const int mrow = wid * 16;
    uint32_t qf[4][4];
#pragma unroll
    for (int c = 0; c < 4; c++) {
        qf[c][0] = S32[(mrow + g) * HSW + c * 8 + tg];
        qf[c][1] = S32[(mrow + 8 + g) * HSW + c * 8 + tg];
        qf[c][2] = S32[(mrow + g) * HSW + c * 8 + tg + 4];
        qf[c][3] = S32[(mrow + 8 + g) * HSW + c * 8 + tg + 4];
    }
    __syncthreads();

    // per-lane ldmatrix offsets:
    // K (non-trans): tsel&2 -> +8 rows, tsel&1 -> +4 words (k-half)
    const int tsel = lane >> 3;
    const int rowi = lane & 7;
    const uint32_t klm =
        (uint32_t)(((tsel & 2) ? 8 : 0) + rowi) * HSW + (uint32_t)((tsel & 1) * 4);
    // V (trans): tsel&1 -> +8 key rows, tsel>>1 -> +4 words (d-half)
    const uint32_t vlm =
        (uint32_t)(((tsel & 1) ? 8 : 0) + rowi) * HSW + (uint32_t)((tsel >> 1) * 4);

    float m_s[2] = {-1e30f, -1e30f};
    float l_s[2] = {0.f, 0.f};
    float oacc[8][4];
#pragma unroll
    for (int ni = 0; ni < 8; ni++)
#pragma unroll
        for (int j = 0; j < 4; j++) oacc[ni][j] = 0.f;

    const int nblocks = qr0 / 64 + 2;

    auto issue = [&](int ib) {
        const int bsel = ib & 1;
        const int kc0  = ib * 64;
        const uint32_t kw = (uint32_t)(bsel * 2 * TILE_WORDS);
        const uint32_t vw = kw + TILE_WORDS;
#pragma unroll
        for (int t = 0; t < 2; t++) {
            int j   = tid + t * 256;
            int row = j >> 3;
            int c8  = j & 7;
            CP_ASYNC16(smb + (kw + row * HSW + c8 * 4) * 4,
                       kb + (size_t)(kc0 + row) * HD_ + c8 * 8);
            CP_ASYNC16(smb + (vw + row * HSW + c8 * 4) * 4,
                       vb + (size_t)(kc0 + row) * HD_ + c8 * 8);
        }
        CP_COMMIT();
    };

    issue(0);

    for (int ib = 0; ib < nblocks; ib++) {
        const int kc0  = ib * 64;
        const int bsel = ib & 1;
        const uint32_t kbase = smb + ((uint32_t)(bsel * 2 * TILE_WORDS) + klm) * 4;
        const uint32_t vbase = smb + ((uint32_t)(bsel * 2 * TILE_WORDS + TILE_WORDS) + vlm) * 4;

        if (ib + 1 < nblocks) { issue(ib + 1); CP_WAIT1(); }
        else                  { CP_WAIT0(); }
        __syncthreads();

        // ---- S = Q K^T ----
        float sacc[8][4];
#pragma unroll
        for (int ni = 0; ni < 8; ni++)
#pragma unroll
            for (int j = 0; j < 4; j++) sacc[ni][j] = 0.f;
#pragma unroll
        for (int c = 0; c < 4; c++) {
#pragma unroll
            for (int p = 0; p < 4; p++) {
                uint32_t b0, b1, b2, b3;
                LDMATRIX_X4(b0, b1, b2, b3,
                            kbase + (uint32_t)(p * 16 * HSW + c * 8) * 4);
                uint32_t bf0[2] = {b0, b1};
                uint32_t bf1[2] = {b2, b3};
                mma_f16(sacc[2 * p],     qf[c], bf0);
                mma_f16(sacc[2 * p + 1], qf[c], bf1);
            }
        }

        // ---- causal mask (near diagonal only) ----
        if (kc0 + 63 > qr0 + mrow) {
#pragma unroll
            for (int ni = 0; ni < 8; ni++) {
#pragma unroll
                for (int j = 0; j < 4; j++) {
                    int row = qr0 + mrow + g + ((j >= 2) ? 8 : 0);
                    int col = kc0 + ni * 8 + tg * 2 + (j & 1);
                    if (col > row) sacc[ni][j] = -1e30f;
                }
            }
        }

        // ---- online softmax; P stays in registers as half2 A-frags ----
        uint32_t pf[8][2];
#pragma unroll
        for (int r = 0; r < 2; r++) {
            float mx = m_s[r];
#pragma unroll
            for (int ni = 0; ni < 8; ni++)
                mx = fmaxf(mx, fmaxf(sacc[ni][r * 2], sacc[ni][r * 2 + 1]));
            mx = fmaxf(mx, __shfl_xor_sync(0xFFFFFFFFu, mx, 1));
            mx = fmaxf(mx, __shfl_xor_sync(0xFFFFFFFFu, mx, 2));
            float alpha = __expf(m_s[r] - mx);
            m_s[r] = mx;
            float sum = 0.f;
#pragma unroll
            for (int ni = 0; ni < 8; ni++) {
                float p0 = __expf(sacc[ni][r * 2]     - mx);
                float p1 = __expf(sacc[ni][r * 2 + 1] - mx);
                sum += p0 + p1;
                pf[ni][r] = h22u(__floats2half2_rn(p0, p1));
            }
            sum += __shfl_xor_sync(0xFFFFFFFFu, sum, 1);
            sum += __shfl_xor_sync(0xFFFFFFFFu, sum, 2);
            l_s[r] = l_s[r] * alpha + sum;
#pragma unroll
            for (int ni = 0; ni < 8; ni++) {
                oacc[ni][r * 2]     *= alpha;
                oacc[ni][r * 2 + 1] *= alpha;
            }
        }

        // ---- O += P V : V natural [key][d], B-frags via ldmatrix.trans ----
#pragma unroll
        for (int c = 0; c < 4; c++) {
            uint32_t af[4] = {pf[2 * c][0], pf[2 * c][1],
                              pf[2 * c + 1][0], pf[2 * c + 1][1]};
#pragma unroll
            for (int p = 0; p < 4; p++) {
                uint32_t b0, b1, b2, b3;
                LDMATRIX_X4_TRANS(b0, b1, b2, b3,
                                  vbase + (uint32_t)(c * 16 * HSW + p * 8) * 4);
                uint32_t bf0[2] = {b0, b1};
                uint32_t bf1[2] = {b2, b3};
                mma_f16(oacc[2 * p],     af, bf0);
                mma_f16(oacc[2 * p + 1], af, bf1);
            }
        }
        __syncthreads();
    }

    // ---- epilogue: normalize, store concat layout as tf32 bits (feeds proj GEMM) ----
    const int b = bh >> 4;
    const int h = bh & 15;
#pragma unroll
    for (int r = 0; r < 2; r++) {
        float inv = 1.f / l_s[r];
        int t = qr0 + mrow + g + r * 8;
        float* dst = g_attn + ((size_t)(b * T_ + t)) * C_ + h * HD_;
#pragma unroll
        for (int ni = 0; ni < 8; ni++) {
            float2 o;
            o.x = __uint_as_float(f2tf32(oacc[ni][r * 2]     * inv));
            o.y = __uint_as_float(f2tf32(oacc[ni][r * 2 + 1] * inv));
            *(float2*)(dst + ni * 8 + tg * 2) = o;
        }
    }
}

// ---------------- LayerNorm; optional tf32-bits twin output ----------------
__global__ __launch_bounds__(256)
void ln_kernel(const float* __restrict__ x, const float* __restrict__ g,
               const float* __restrict__ beta, float* __restrict__ y,
               float* __restrict__ y_t) {
    const int row = blockIdx.x;
    const int tid = threadIdx.x;
    const float* xr = x + (size_t)row * C_;

    float4 v = *(const float4*)(xr + tid * 4);
    float s  = v.x + v.y + v.z + v.w;
    float s2 = v.x * v.x + v.y * v.y + v.z * v.z + v.w * v.w;
#pragma unroll
    for (int o = 16; o > 0; o >>= 1) {
        s  += __shfl_xor_sync(0xFFFFFFFFu, s, o);
        s2 += __shfl_xor_sync(0xFFFFFFFFu, s2, o);
    }
    __shared__ float sh[16];
    __shared__ float mean_sh, istd_sh;
    int w = tid >> 5, l = tid & 31;
    if (l == 0) { sh[w] = s; sh[w + 8] = s2; }
    __syncthreads();
    if (tid == 0) {
        float ts = 0.f, ts2 = 0.f;
#pragma unroll
        for (int i = 0; i < 8; i++) { ts += sh[i]; ts2 += sh[i + 8]; }
        float mean = ts * (1.f / C_);
        float var  = ts2 * (1.f / C_) - mean * mean;
        mean_sh = mean;
        istd_sh = rsqrtf(var + 1e-5f);
    }
    __syncthreads();
    float mean = mean_sh, istd = istd_sh;
    float4 gv = *(const float4*)(g + tid * 4);
    float4 bv = *(const float4*)(beta + tid * 4);
    float4 out;
    out.x = (v.x - mean) * istd * gv.x + bv.x;
    out.y = (v.y - mean) * istd * gv.y + bv.y;
    out.z = (v.z - mean) * istd * gv.z + bv.z;
    out.w = (v.w - mean) * istd * gv.w + bv.w;
    *(float4*)(y + (size_t)row * C_ + tid * 4) = out;
    if (y_t) {
        uint4 ot;
        ot.x = f2tf32(out.x); ot.y = f2tf32(out.y);
        ot.z = f2tf32(out.z); ot.w = f2tf32(out.w);
        *(uint4*)(y_t + (size_t)row * C_ + tid * 4) = ot;
    }
}

// ---------------- launch ----------------
extern "C" void kernel_launch(void* const* d_in, const int* in_sizes, int n_in,
                              void* d_out, int out_size) {
    (void)in_sizes; (void)n_in; (void)out_size;
    const float* x   = (const float*)d_in[0];
    const float* Wq  = (const float*)d_in[1];
    const float* Wk  = (const float*)d_in[2];
    const float* Wv  = (const float*)d_in[3];
    const float* Wp  = (const float*)d_in[4];
    const float* bp  = (const float*)d_in[5];
    const float* W1  = (const float*)d_in[6];
    const float* b1  = (const float*)d_in[7];
    const float* W2  = (const float*)d_in[8];
    const float* b2  = (const float*)d_in[9];
    const float* g1  = (const float*)d_in[10];
    const float* be1 = (const float*)d_in[11];
    const float* g2  = (const float*)d_in[12];
    const float* be2 = (const float*)d_in[13];

    void *p_xt_, *p_Wpt_, *p_W1t_, *p_W2t_, *p_wqkv_, *p_attn_, *p_h1_, *p_x1_, *p_x1t_, *p_ff_, *p_h2_;
    cudaGetSymbolAddress(&p_xt_,   g_xt);
    cudaGetSymbolAddress(&p_Wpt_,  g_Wpt);
    cudaGetSymbolAddress(&p_W1t_,  g_W1t);
    cudaGetSymbolAddress(&p_W2t_,  g_W2t);
    cudaGetSymbolAddress(&p_wqkv_, g_Wqkv);
    cudaGetSymbolAddress(&p_attn_, g_attn);
    cudaGetSymbolAddress(&p_h1_,   g_h1);
    cudaGetSymbolAddress(&p_x1_,   g_x1);
    cudaGetSymbolAddress(&p_x1t_,  g_x1t);
    cudaGetSymbolAddress(&p_ff_,   g_ff);
    cudaGetSymbolAddress(&p_h2_,   g_h2);
    float* p_xt   = (float*)p_xt_;
    float* p_Wpt  = (float*)p_Wpt_;
    float* p_W1t  = (float*)p_W1t_;
    float* p_W2t  = (float*)p_W2t_;
    float* p_wqkv = (float*)p_wqkv_;
    float* p_attn = (float*)p_attn_;
    float* p_h1   = (float*)p_h1_;
    float* p_x1   = (float*)p_x1_;
    float* p_x1t  = (float*)p_x1t_;
    float* p_ff   = (float*)p_ff_;
    float* p_h2   = (float*)p_h2_;

    cudaFuncSetAttribute(attn_tc_kernel,
                         cudaFuncAttributeMaxDynamicSharedMemorySize, ATTN_SMEM_BYTES);
    cudaFuncSetAttribute(gemm_tc<EPI_QKV>,
                         cudaFuncAttributeMaxDynamicSharedMemorySize, GEMM_SMEM_BYTES);
    cudaFuncSetAttribute(gemm_tc<EPI_BIAS_RELU>,
                         cudaFuncAttributeMaxDynamicSharedMemorySize, GEMM_SMEM_BYTES);
    cudaFuncSetAttribute(gemm_tc<EPI_BIAS_RES>,
                         cudaFuncAttributeMaxDynamicSharedMemorySize, GEMM_SMEM_BYTES);

    // 0. tf32 pre-conversions (x, Wp, W1, W2)
    cvt_tf32_kernel<<<(M_ * C_ / 4 + 255) / 256, 256>>>(x,  p_xt,  M_ * C_ / 4);
    cvt_tf32_kernel<<<(C_ * C_ / 4 + 255) / 256, 256>>>(Wp, p_Wpt, C_ * C_ / 4);
    cvt_tf32_kernel<<<(C_ * FF_ / 4 + 255) / 256, 256>>>(W1, p_W1t, C_ * FF_ / 4);
    cvt_tf32_kernel<<<(FF_ * C_ / 4 + 255) / 256, 256>>>(W2, p_W2t, FF_ * C_ / 4);
    // 1. pack qkv weights -> [C, 3C] tf32 bits
    pack_qkv_kernel<<<(C_ * 3 * C_ + 255) / 256, 256>>>(Wq, Wk, Wv);
    // 2. QKV projection, epilogue converts to fp16 (Q scaled; V natural)
    gemm_tc<EPI_QKV><<<dim3(3 * C_ / BN, M_ / BM), 256, GEMM_SMEM_BYTES>>>(
        p_xt, p_wqkv, nullptr, nullptr, nullptr, M_, 3 * C_, C_);
    // 3. causal attention -> tf32-bit concat output
    attn_tc_kernel<<<dim3(T_ / 128, B_ * H_), 256, ATTN_SMEM_BYTES>>>();
    // 4. out proj + bias + residual (raw f32 out)
    gemm_tc<EPI_BIAS_RES><<<dim3(C_ / BN, M_ / BM), 256, GEMM_SMEM_BYTES>>>(
        p_attn, p_Wpt, bp, x, p_h1, M_, C_, C_);
    // 5. LN1 (raw + tf32 twin)
    ln_kernel<<<M_, 256>>>(p_h1, g1, be1, p_x1, p_x1t);
    // 6. FFN up + relu (tf32-bit out)
    gemm_tc<EPI_BIAS_RELU><<<dim3(FF_ / BN, M_ / BM), 256, GEMM_SMEM_BYTES>>>(
        p_x1t, p_W1t, b1, nullptr, p_ff, M_, FF_, C_);
    // 7. FFN down + bias + residual (raw f32 out)
    gemm_tc<EPI_BIAS_RES><<<dim3(C_ / BN, M_ / BM), 256, GEMM_SMEM_BYTES>>>(
        p_ff, p_W2t, b2, p_x1, p_h2, M_, C_, FF_);
    // 8. LN2 -> d_out
    ln_kernel<<<M_, 256>>>(p_h2, g2, be2, (float*)d_out, nullptr);
}

// round 11
// speedup vs baseline: 4.0716x; 1.0210x over previous
#include <cuda_runtime.h>
#include <cuda_fp16.h>
#include <cstdint>
#include <cmath>

#define B_  2
#define T_  2048
#define C_  1024
#define H_  16
#define HD_ 64
#define M_  (B_ * T_)     // 4096 rows
#define FF_ (4 * C_)      // 4096

// ---------------- scratch (static device allocations; allowed) ----------------
__device__ float  g_Wqkv[C_ * 3 * C_];           // packed [C, 3C] qkv weight (tf32 bits)
__device__ float  g_xt[M_ * C_];                 // x converted to tf32 bits
__device__ float  g_Wpt[C_ * C_];                // Wp tf32 bits
__device__ float  g_W1t[C_ * FF_];               // W1 tf32 bits
__device__ float  g_W2t[FF_ * C_];               // W2 tf32 bits
__device__ __half g_qh[B_ * H_ * T_ * HD_];      // [b,h][t][d], pre-scaled 0.125
__device__ __half g_kh[B_ * H_ * T_ * HD_];      // [b,h][t][d]
__device__ __half g_vh[B_ * H_ * T_ * HD_];      // [b,h][t][d] (natural layout)
__device__ float  g_attn[M_ * C_];               // attention out (tf32 bits)
__device__ float  g_h1[M_ * C_];                 // raw f32
__device__ float  g_x1[M_ * C_];                 // LN1 out raw f32
__device__ float  g_x1t[M_ * C_];                // LN1 out tf32 bits
__device__ float  g_ff[M_ * FF_];                // relu(x1 W1 + b1) tf32 bits
__device__ float  g_h2[M_ * C_];                 // raw f32

// ---------------- helpers ----------------
__device__ __forceinline__ uint32_t f2tf32(float f) {
    uint32_t r;
    asm("cvt.rna.tf32.f32 %0, %1;" : "=r"(r) : "f"(f));
    return r;
}
__device__ __forceinline__ uint32_t pack_half2(float lo, float hi) {
    uint32_t r;
    asm("{ .reg .f16 l, h; cvt.rn.f16.f32 l, %1; cvt.rn.f16.f32 h, %2; mov.b32 %0, {l, h}; }"
        : "=r"(r) : "f"(lo), "f"(hi));
    return r;
}
__device__ __forceinline__ void mma_tf32(float* d, const uint32_t* a, const uint32_t* b) {
    asm volatile(
        "mma.sync.aligned.m16n8k8.row.col.f32.tf32.tf32.f32 "
        "{%0,%1,%2,%3}, {%4,%5,%6,%7}, {%8,%9}, {%0,%1,%2,%3};\n"
        : "+f"(d[0]), "+f"(d[1]), "+f"(d[2]), "+f"(d[3])
        : "r"(a[0]), "r"(a[1]), "r"(a[2]), "r"(a[3]),
          "r"(b[0]), "r"(b[1]));
}
__device__ __forceinline__ void mma_f16(float* d, const uint32_t* a, const uint32_t* b) {
    asm volatile(
        "mma.sync.aligned.m16n8k16.row.col.f32.f16.f16.f32 "
        "{%0,%1,%2,%3}, {%4,%5,%6,%7}, {%8,%9}, {%0,%1,%2,%3};\n"
        : "+f"(d[0]), "+f"(d[1]), "+f"(d[2]), "+f"(d[3])
        : "r"(a[0]), "r"(a[1]), "r"(a[2]), "r"(a[3]),
          "r"(b[0]), "r"(b[1]));
}
__device__ __forceinline__ uint32_t smem_u32(const void* p) {
    uint32_t a;
    asm("{ .reg .u64 t; cvta.to.shared.u64 t, %1; cvt.u32.u64 %0, t; }" : "=r"(a) : "l"(p));
    return a;
}
#define LDMATRIX_X4(r0, r1, r2, r3, addr) \
    asm volatile("ldmatrix.sync.aligned.m8n8.x4.shared.b16 {%0,%1,%2,%3}, [%4];" \
        : "=r"(r0), "=r"(r1), "=r"(r2), "=r"(r3) : "r"(addr))
#define LDMATRIX_X4_TRANS(r0, r1, r2, r3, addr) \
    asm volatile("ldmatrix.sync.aligned.m8n8.x4.trans.shared.b16 {%0,%1,%2,%3}, [%4];" \
        : "=r"(r0), "=r"(r1), "=r"(r2), "=r"(r3) : "r"(addr))
#define CP_ASYNC16(dst_u32, src_ptr) \
    asm volatile("cp.async.ca.shared.global [%0], [%1], 16;\n" \
        :: "r"(dst_u32), "l"(__cvta_generic_to_global(src_ptr)) : "memory")
#define CP_COMMIT() asm volatile("cp.async.commit_group;\n" ::: "memory")
#define CP_WAIT0()  asm volatile("cp.async.wait_group 0;\n" ::: "memory")
#define CP_WAIT1()  asm volatile("cp.async.wait_group 1;\n" ::: "memory")

// ---------------- tf32 convert kernel ----------------
__global__ void cvt_tf32_kernel(const float* __restrict__ in, float* __restrict__ out, int n4) {
    int i = blockIdx.x * blockDim.x + threadIdx.x;
    if (i >= n4) return;
    float4 v = ((const float4*)in)[i];
    uint4 o;
    o.x = f2tf32(v.x); o.y = f2tf32(v.y); o.z = f2tf32(v.z); o.w = f2tf32(v.w);
    ((uint4*)out)[i] = o;
}

// ---------------- weight pack (stores tf32 bits) ----------------
__global__ void pack_qkv_kernel(const float* __restrict__ Wq,
                                const float* __restrict__ Wk,
                                const float* __restrict__ Wv) {
    int idx = blockIdx.x * blockDim.x + threadIdx.x;
    if (idx >= C_ * 3 * C_) return;
    int c   = idx / (3 * C_);
    int rem = idx - c * (3 * C_);
    int s   = rem >> 10;
    int r2  = rem & 1023;
    int h   = r2 >> 6;
    int d   = r2 & 63;
    const float* W = (s == 0) ? Wq : ((s == 1) ? Wk : Wv);
    g_Wqkv[idx] = __uint_as_float(f2tf32(W[(h * C_ + c) * HD_ + d]));
}

// ============ tf32 GEMM v2: cp.async 3-stage pipeline, 2 CTAs/SM ============
constexpr int EPI_QKV       = 0;
constexpr int EPI_BIAS_RELU = 1;
constexpr int EPI_BIAS_RES  = 2;

#define BM 128
#define BN 128
#define BK 32
#define ASW 36
#define BSW 136
#define A_TILE_W (BM * ASW)
#define B_TILE_W (BK * BSW)
#define STAGE_W  (A_TILE_W + B_TILE_W)
#define GEMM_SMEM_BYTES (3 * STAGE_W * 4)

template <int EPI>
__global__ __launch_bounds__(256, 2)
void gemm_tc(const float* __restrict__ A, const float* __restrict__ Bmat,
             const float* __restrict__ bias, const float* __restrict__ res,
             float* __restrict__ Cout, int M, int N, int K) {
    extern __shared__ __align__(16) char smraw[];
    uint32_t* S32 = (uint32_t*)smraw;
    const uint32_t smb = smem_u32(smraw);

    const int tid = threadIdx.x;
    const int wid = tid >> 5;
    const int lane = tid & 31;
    const int g  = lane >> 2;
    const int tg = lane & 3;
    const int wm = (wid >> 2) * 64;
    const int wn = (wid & 3) * 32;
    const int bm = blockIdx.y * BM;
    const int bn = blockIdx.x * BN;

    float acc[4][4][4];
#pragma unroll
    for (int mi = 0; mi < 4; mi++)
#pragma unroll
        for (int ni = 0; ni < 4; ni++)
#pragma unroll
            for (int j = 0; j < 4; j++) acc[mi][ni][j] = 0.f;

    const int KT = K / BK;

    auto issue = [&](int kt) {
        if (kt < KT) {
            const int k0 = kt * BK;
            const uint32_t base = (uint32_t)((kt % 3) * STAGE_W);
#pragma unroll
            for (int i = 0; i < 4; i++) {
                int f = i * 256 + tid;
                int r = f >> 3, c = f & 7;
                CP_ASYNC16(smb + (base + r * ASW + c * 4) * 4,
                           A + (size_t)(bm + r) * K + k0 + c * 4);
            }
#pragma unroll
            for (int i = 0; i < 4; i++) {
                int f = i * 256 + tid;
                int k = f >> 5, n4 = f & 31;
                CP_ASYNC16(smb + (base + A_TILE_W + k * BSW + n4 * 4) * 4,
                           Bmat + (size_t)(k0 + k) * N + bn + n4 * 4);
            }
        }
        CP_COMMIT();
    };

    issue(0);
    issue(1);

    for (int kt = 0; kt < KT; ++kt) {
        CP_WAIT1();
        __syncthreads();
        issue(kt + 2);

        const uint32_t* Abuf = S32 + (kt % 3) * STAGE_W;
        const uint32_t* Bbuf = Abuf + A_TILE_W;

#pragma unroll
        for (int kk8 = 0; kk8 < 4; kk8++) {
            const int kk = kk8 * 8;
            uint32_t af[4][4], bf[4][2];
#pragma unroll
            for (int mi = 0; mi < 4; mi++) {
                int m0 = wm + mi * 16 + g;
                af[mi][0] = Abuf[m0 * ASW + kk + tg];
                af[mi][1] = Abuf[(m0 + 8) * ASW + kk + tg];
                af[mi][2] = Abuf[m0 * ASW + kk + tg + 4];
                af[mi][3] = Abuf[(m0 + 8) * ASW + kk + tg + 4];
            }
#pragma unroll
            for (int ni = 0; ni < 4; ni++) {
                int n0 = wn + ni * 8 + g;
                bf[ni][0] = Bbuf[(kk + tg) * BSW + n0];
                bf[ni][1] = Bbuf[(kk + tg + 4) * BSW + n0];
            }
#pragma unroll
            for (int mi = 0; mi < 4; mi++)
#pragma unroll
                for (int ni = 0; ni < 4; ni++)
                    mma_tf32(acc[mi][ni], af[mi], bf[ni]);
        }
    }

#pragma unroll
    for (int mi = 0; mi < 4; mi++) {
#pragma unroll
        for (int ni = 0; ni < 4; ni++) {
#pragma unroll
            for (int half = 0; half < 2; half++) {
                int row = bm + wm + mi * 16 + g + half * 8;
                int col = bn + wn + ni * 8 + tg * 2;
                float v0 = acc[mi][ni][half * 2 + 0];
                float v1 = acc[mi][ni][half * 2 + 1];
                if (EPI == EPI_QKV) {
                    int s  = col >> 10;
                    int h  = (col >> 6) & (H_ - 1);
                    int d0 = col & 63;
                    int bb = row >> 11;
                    int t  = row & 2047;
                    size_t off = (((size_t)(bb * H_ + h) * T_) + t) * HD_ + d0;
                    if (s == 0) {
                        *(__half2*)(g_qh + off) = __floats2half2_rn(v0 * 0.125f, v1 * 0.125f);
                    } else if (s == 1) {
                        *(__half2*)(g_kh + off) = __floats2half2_rn(v0, v1);
                    } else {
                        *(__half2*)(g_vh + off) = __floats2half2_rn(v0, v1);
                    }
                } else if (EPI == EPI_BIAS_RELU) {
                    float2 bv = *(const float2*)(bias + col);
                    float2 o;
                    o.x = __uint_as_float(f2tf32(fmaxf(v0 + bv.x, 0.f)));
                    o.y = __uint_as_float(f2tf32(fmaxf(v1 + bv.y, 0.f)));
                    *(float2*)(Cout + (size_t)row * N + col) = o;
                } else {
                    float2 bv = *(const float2*)(bias + col);
                    float2 rv = *(const float2*)(res + (size_t)row * N + col);
                    float2 o = make_float2(v0 + bv.x + rv.x, v1 + bv.y + rv.y);
                    *(float2*)(Cout + (size_t)row * N + col) = o;
                }
            }
        }
    }
}

// ====== fp16 TC flash attention: 64 q-rows/CTA, 4 warps, 4 CTAs/SM, no spills ======
#define HSW 36                                   // row stride in 32-bit words
#define TILE_WORDS (64 * HSW)                    // 2304 words
#define ATTN_SMEM_BYTES (4 * TILE_WORDS * 4)     // 36864 B (K/V double buffer)

__global__ __launch_bounds__(128, 4)
void attn_tc_kernel() {
    extern __shared__ __align__(16) char smraw[];
    uint32_t* S32 = (uint32_t*)smraw;
    const uint32_t smb = smem_u32(smraw);

    const int tid  = threadIdx.x;
    const int wid  = tid >> 5;                   // 0..3
    const int lane = tid & 31;
    const int g    = lane >> 2;
    const int tg   = lane & 3;
    const int bh   = blockIdx.y;
    const int qi   = gridDim.x - 1 - blockIdx.x; // heavy tiles first
    const int qr0  = qi * 64;

    const __half* qb = g_qh + (size_t)bh * T_ * HD_;
    const __half* kb = g_kh + (size_t)bh * T_ * HD_;
    const __half* vb = g_vh + (size_t)bh * T_ * HD_;

    // ---- stage Q (64 rows) through buffer 0, extract frags, free it ----
    for (int j = tid; j < 512; j += 128) {       // 64 rows x 8 uint4-of-halfs
        int r  = j >> 3;
        int c8 = j & 7;
        uint4 v = *(const uint4*)(qb + (size_t)(qr0 + r) * HD_ + c8 * 8);
        *(uint4*)(S32 + r * HSW + c8 * 4) = v;
    }
    __syncthreads();
    const int mrow = wid * 16;
    uint32_t qf[4][4];
#pragma unroll
    for (int c = 0; c < 4; c++) {
        qf[c][0] = S32[(mrow + g) * HSW + c * 8 + tg];
        qf[c][1] = S32[(mrow + 8 + g) * HSW + c * 8 + tg];
        qf[c][2] = S32[(mrow + g) * HSW + c * 8 + tg + 4];
        qf[c][3] = S32[(mrow + 8 + g) * HSW + c * 8 + tg + 4];
    }
    __syncthreads();

    // per-lane ldmatrix offsets
    const int tsel = lane >> 3;
    const int rowi = lane & 7;
    const uint32_t klm =
        (uint32_t)(((tsel & 2) ? 8 : 0) + rowi) * HSW + (uint32_t)((tsel & 1) * 4);
    const uint32_t vlm =
        (uint32_t)(((tsel & 1) ? 8 : 0) + rowi) * HSW + (uint32_t)((tsel >> 1) * 4);

    float m_s[2] = {-1e30f, -1e30f};
    float l_s[2] = {0.f, 0.f};
    float oacc[8][4];
#pragma unroll
    for (int ni = 0; ni < 8; ni++)
#pragma unroll
        for (int j = 0; j < 4; j++) oacc[ni][j] = 0.f;

    const int nblocks = qi + 1;                  // keys 0 .. 64*qi+63

    auto issue = [&](int ib) {
        const int bsel = ib & 1;
        const int kc0  = ib * 64;
        const uint32_t kw = (uint32_t)(bsel * 2 * TILE_WORDS);
        const uint32_t vw = kw + TILE_WORDS;
#pragma unroll
        for (int t = 0; t < 4; t++) {
            int j   = tid + t * 128;             // 0..511
            int row = j >> 3;
            int c8  = j & 7;
            CP_ASYNC16(smb + (kw + row * HSW + c8 * 4) * 4,
                       kb + (size_t)(kc0 + row) * HD_ + c8 * 8);
            CP_ASYNC16(smb + (vw + row * HSW + c8 * 4) * 4,
                       vb + (size_t)(kc0 + row) * HD_ + c8 * 8);
        }
        CP_COMMIT();
    };

    issue(0);

    for (int ib = 0; ib < nblocks; ib++) {
        const int kc0  = ib * 64;
        const int bsel = ib & 1;
        const uint32_t kbase = smb + ((uint32_t)(bsel * 2 * TILE_WORDS) + klm) * 4;
        const uint32_t vbase = smb + ((uint32_t)(bsel * 2 * TILE_WORDS + TILE_WORDS) + vlm) * 4;

        if (ib + 1 < nblocks) { issue(ib + 1); CP_WAIT1(); }
        else                  { CP_WAIT0(); }
        __syncthreads();

        // ---- S = Q K^T ----
        float sacc[8][4];
#pragma unroll
        for (int ni = 0; ni < 8; ni++)
#pragma unroll
            for (int j = 0; j < 4; j++) sacc[ni][j] = 0.f;
#pragma unroll
        for (int c = 0; c < 4; c++) {
#pragma unroll
            for (int p = 0; p < 4; p++) {
                uint32_t b0, b1, b2, b3;
                LDMATRIX_X4(b0, b1, b2, b3,
                            kbase + (uint32_t)(p * 16 * HSW + c * 8) * 4);
                uint32_t bf0[2] = {b0, b1};
                uint32_t bf1[2] = {b2, b3};
                mma_f16(sacc[2 * p],     qf[c], bf0);
                mma_f16(sacc[2 * p + 1], qf[c], bf1);
            }
        }

        // ---- causal mask (near diagonal only) ----
        if (kc0 + 63 > qr0 + mrow) {
#pragma unroll
            for (int ni = 0; ni < 8; ni++) {
#pragma unroll
                for (int j = 0; j < 4; j++) {
                    int row = qr0 + mrow + g + ((j >= 2) ? 8 : 0);
                    int col = kc0 + ni * 8 + tg * 2 + (j & 1);
                    if (col > row) sacc[ni][j] = -1e30f;
                }
            }
        }

        // ---- online softmax; packed P overwrites dead sacc slots (no extra regs) ----
#pragma unroll
        for (int r = 0; r < 2; r++) {
            // max tree over 16 values
            float mx0 = fmaxf(fmaxf(sacc[0][r*2], sacc[0][r*2+1]),
                              fmaxf(sacc[1][r*2], sacc[1][r*2+1]));
            float mx1 = fmaxf(fmaxf(sacc[2][r*2], sacc[2][r*2+1]),
                              fmaxf(sacc[3][r*2], sacc[3][r*2+1]));
            float mx2 = fmaxf(fmaxf(sacc[4][r*2], sacc[4][r*2+1]),
                              fmaxf(sacc[5][r*2], sacc[5][r*2+1]));
            float mx3 = fmaxf(fmaxf(sacc[6][r*2], sacc[6][r*2+1]),
                              fmaxf(sacc[7][r*2], sacc[7][r*2+1]));
            float mx = fmaxf(fmaxf(mx0, mx1), fmaxf(mx2, mx3));
            mx = fmaxf(mx, m_s[r]);
            mx = fmaxf(mx, __shfl_xor_sync(0xFFFFFFFFu, mx, 1));
            mx = fmaxf(mx, __shfl_xor_sync(0xFFFFFFFFu, mx, 2));
            float alpha = __expf(m_s[r] - mx);
            m_s[r] = mx;
            float sum = 0.f;
#pragma unroll
            for (int ni = 0; ni < 8; ni++) {
                float p0 = __expf(sacc[ni][r * 2]     - mx);
                float p1 = __expf(sacc[ni][r * 2 + 1] - mx);
                sum += p0 + p1;
                sacc[ni][r * 2] = __uint_as_float(pack_half2(p0, p1));  // P bits
            }
            sum += __shfl_xor_sync(0xFFFFFFFFu, sum, 1);
            sum += __shfl_xor_sync(0xFFFFFFFFu, sum, 2);
            l_s[r] = l_s[r] * alpha + sum;
#pragma unroll
            for (int ni = 0; ni < 8; ni++) {
                oacc[ni][r * 2]     *= alpha;
                oacc[ni][r * 2 + 1] *= alpha;
            }
        }

        // ---- O += P V : A-frags from packed sacc slots ----
#pragma unroll
        for (int c = 0; c < 4; c++) {
            uint32_t af[4] = {__float_as_uint(sacc[2 * c][0]),
                              __float_as_uint(sacc[2 * c][2]),
                              __float_as_uint(sacc[2 * c + 1][0]),
                              __float_as_uint(sacc[2 * c + 1][2])};
#pragma unroll
            for (int p = 0; p < 4; p++) {
                uint32_t b0, b1, b2, b3;
                LDMATRIX_X4_TRANS(b0, b1, b2, b3,
                                  vbase + (uint32_t)(c * 16 * HSW + p * 8) * 4);
                uint32_t bf0[2] = {b0, b1};
                uint32_t bf1[2] = {b2, b3};
                mma_f16(oacc[2 * p],     af, bf0);
                mma_f16(oacc[2 * p + 1], af, bf1);
            }
        }
        __syncthreads();
    }

    // ---- epilogue: normalize, store concat layout as tf32 bits ----
    const int b = bh >> 4;
    const int h = bh & 15;
#pragma unroll
    for (int r = 0; r < 2; r++) {
        float inv = 1.f / l_s[r];
        int t = qr0 + mrow + g + r * 8;
        float* dst = g_attn + ((size_t)(b * T_ + t)) * C_ + h * HD_;
#pragma unroll
        for (int ni = 0; ni < 8; ni++) {
            float2 o;
            o.x = __uint_as_float(f2tf32(oacc[ni][r * 2]     * inv));
            o.y = __uint_as_float(f2tf32(oacc[ni][r * 2 + 1] * inv));
            *(float2*)(dst + ni * 8 + tg * 2) = o;
        }
    }
}

// ---------------- LayerNorm; optional tf32-bits twin output ----------------
__global__ __launch_bounds__(256)
void ln_kernel(const float* __restrict__ x, const float* __restrict__ g,
               const float* __restrict__ beta, float* __restrict__ y,
               float* __restrict__ y_t) {
    const int row = blockIdx.x;
    const int tid = threadIdx.x;
    const float* xr = x + (size_t)row * C_;

    float4 v = *(const float4*)(xr + tid * 4);
    float s  = v.x + v.y + v.z + v.w;
    float s2 = v.x * v.x + v.y * v.y + v.z * v.z + v.w * v.w;
#pragma unroll
    for (int o = 16; o > 0; o >>= 1) {
        s  += __shfl_xor_sync(0xFFFFFFFFu, s, o);
        s2 += __shfl_xor_sync(0xFFFFFFFFu, s2, o);
    }
    __shared__ float sh[16];
    __shared__ float mean_sh, istd_sh;
    int w = tid >> 5, l = tid & 31;
    if (l == 0) { sh[w] = s; sh[w + 8] = s2; }
    __syncthreads();
    if (tid == 0) {
        float ts = 0.f, ts2 = 0.f;
#pragma unroll
        for (int i = 0; i < 8; i++) { ts += sh[i]; ts2 += sh[i + 8]; }
        float mean = ts * (1.f / C_);
        float var  = ts2 * (1.f / C_) - mean * mean;
        mean_sh = mean;
        istd_sh = rsqrtf(var + 1e-5f);
    }
    __syncthreads();
    float mean = mean_sh, istd = istd_sh;
    float4 gv = *(const float4*)(g + tid * 4);
    float4 bv = *(const float4*)(beta + tid * 4);
    float4 out;
    out.x = (v.x - mean) * istd * gv.x + bv.x;
    out.y = (v.y - mean) * istd * gv.y + bv.y;
    out.z = (v.z - mean) * istd * gv.z + bv.z;
    out.w = (v.w - mean) * istd * gv.w + bv.w;
    *(float4*)(y + (size_t)row * C_ + tid * 4) = out;
    if (y_t) {
        uint4 ot;
        ot.x = f2tf32(out.x); ot.y = f2tf32(out.y);
        ot.z = f2tf32(out.z); ot.w = f2tf32(out.w);
        *(uint4*)(y_t + (size_t)row * C_ + tid * 4) = ot;
    }
}

// ---------------- launch ----------------
extern "C" void kernel_launch(void* const* d_in, const int* in_sizes, int n_in,
                              void* d_out, int out_size) {
    (void)in_sizes; (void)n_in; (void)out_size;
    const float* x   = (const float*)d_in[0];
    const float* Wq  = (const float*)d_in[1];
    const float* Wk  = (const float*)d_in[2];
    const float* Wv  = (const float*)d_in[3];
    const float* Wp  = (const float*)d_in[4];
    const float* bp  = (const float*)d_in[5];
    const float* W1  = (const float*)d_in[6];
    const float* b1  = (const float*)d_in[7];
    const float* W2  = (const float*)d_in[8];
    const float* b2  = (const float*)d_in[9];
    const float* g1  = (const float*)d_in[10];
    const float* be1 = (const float*)d_in[11];
    const float* g2  = (const float*)d_in[12];
    const float* be2 = (const float*)d_in[13];

    void *p_xt_, *p_Wpt_, *p_W1t_, *p_W2t_, *p_wqkv_, *p_attn_, *p_h1_, *p_x1_, *p_x1t_, *p_ff_, *p_h2_;
    cudaGetSymbolAddress(&p_xt_,   g_xt);
    cudaGetSymbolAddress(&p_Wpt_,  g_Wpt);
    cudaGetSymbolAddress(&p_W1t_,  g_W1t);
    cudaGetSymbolAddress(&p_W2t_,  g_W2t);
    cudaGetSymbolAddress(&p_wqkv_, g_Wqkv);
    cudaGetSymbolAddress(&p_attn_, g_attn);
    cudaGetSymbolAddress(&p_h1_,   g_h1);
    cudaGetSymbolAddress(&p_x1_,   g_x1);
    cudaGetSymbolAddress(&p_x1t_,  g_x1t);
    cudaGetSymbolAddress(&p_ff_,   g_ff);
    cudaGetSymbolAddress(&p_h2_,   g_h2);
    float* p_xt   = (float*)p_xt_;
    float* p_Wpt  = (float*)p_Wpt_;
    float* p_W1t  = (float*)p_W1t_;
    float* p_W2t  = (float*)p_W2t_;
    float* p_wqkv = (float*)p_wqkv_;
    float* p_attn = (float*)p_attn_;
    float* p_h1   = (float*)p_h1_;
    float* p_x1   = (float*)p_x1_;
    float* p_x1t  = (float*)p_x1t_;
    float* p_ff   = (float*)p_ff_;
    float* p_h2   = (float*)p_h2_;

    cudaFuncSetAttribute(attn_tc_kernel,
                         cudaFuncAttributeMaxDynamicSharedMemorySize, ATTN_SMEM_BYTES);
    cudaFuncSetAttribute(gemm_tc<EPI_QKV>,
                         cudaFuncAttributeMaxDynamicSharedMemorySize, GEMM_SMEM_BYTES);
    cudaFuncSetAttribute(gemm_tc<EPI_BIAS_RELU>,
                         cudaFuncAttributeMaxDynamicSharedMemorySize, GEMM_SMEM_BYTES);
    cudaFuncSetAttribute(gemm_tc<EPI_BIAS_RES>,
                         cudaFuncAttributeMaxDynamicSharedMemorySize, GEMM_SMEM_BYTES);

    // 0. tf32 pre-conversions (x, Wp, W1, W2)
    cvt_tf32_kernel<<<(M_ * C_ / 4 + 255) / 256, 256>>>(x,  p_xt,  M_ * C_ / 4);
    cvt_tf32_kernel<<<(C_ * C_ / 4 + 255) / 256, 256>>>(Wp, p_Wpt, C_ * C_ / 4);
    cvt_tf32_kernel<<<(C_ * FF_ / 4 + 255) / 256, 256>>>(W1, p_W1t, C_ * FF_ / 4);
    cvt_tf32_kernel<<<(FF_ * C_ / 4 + 255) / 256, 256>>>(W2, p_W2t, FF_ * C_ / 4);
    // 1. pack qkv weights -> [C, 3C] tf32 bits
    pack_qkv_kernel<<<(C_ * 3 * C_ + 255) / 256, 256>>>(Wq, Wk, Wv);
    // 2. QKV projection, epilogue converts to fp16
    gemm_tc<EPI_QKV><<<dim3(3 * C_ / BN, M_ / BM), 256, GEMM_SMEM_BYTES>>>(
        p_xt, p_wqkv, nullptr, nullptr, nullptr, M_, 3 * C_, C_);
    // 3. causal attention (64-row tiles, 4 CTAs/SM) -> tf32-bit concat output
    attn_tc_kernel<<<dim3(T_ / 64, B_ * H_), 128, ATTN_SMEM_BYTES>>>();
    // 4. out proj + bias + residual
    gemm_tc<EPI_BIAS_RES><<<dim3(C_ / BN, M_ / BM), 256, GEMM_SMEM_BYTES>>>(
        p_attn, p_Wpt, bp, x, p_h1, M_, C_, C_);
    // 5. LN1 (raw + tf32 twin)
    ln_kernel<<<M_, 256>>>(p_h1, g1, be1, p_x1, p_x1t);
    // 6. FFN up + relu (tf32-bit out)
    gemm_tc<EPI_BIAS_RELU><<<dim3(FF_ / BN, M_ / BM), 256, GEMM_SMEM_BYTES>>>(
        p_x1t, p_W1t, b1, nullptr, p_ff, M_, FF_, C_);
    // 7. FFN down + bias + residual
    gemm_tc<EPI_BIAS_RES><<<dim3(C_ / BN, M_ / BM), 256, GEMM_SMEM_BYTES>>>(
        p_ff, p_W2t, b2, p_x1, p_h2, M_, C_, FF_);
    // 8. LN2 -> d_out
    ln_kernel<<<M_, 256>>>(p_h2, g2, be2, (float*)d_out, nullptr);
}

// round 13
// speedup vs baseline: 4.1052x; 1.0082x over previous
#include <cuda_runtime.h>
#include <cuda_fp16.h>
#include <cstdint>
#include <cmath>

#define B_  2
#define T_  2048
#define C_  1024
#define H_  16
#define HD_ 64
#define M_  (B_ * T_)     // 4096 rows
#define FF_ (4 * C_)      // 4096

// ---------------- scratch (static device allocations; allowed) ----------------
__device__ float  g_Wqkv[C_ * 3 * C_];           // packed [C, 3C] qkv weight (tf32 bits)
__device__ float  g_xt[M_ * C_];                 // x converted to tf32 bits
__device__ float  g_Wpt[C_ * C_];                // Wp tf32 bits
__device__ float  g_W1t[C_ * FF_];               // W1 tf32 bits
__device__ float  g_W2t[FF_ * C_];               // W2 tf32 bits
__device__ __half g_qh[B_ * H_ * T_ * HD_];      // [b,h][t][d], pre-scaled 0.125*log2e
__device__ __half g_kh[B_ * H_ * T_ * HD_];      // [b,h][t][d]
__device__ __half g_vh[B_ * H_ * T_ * HD_];      // [b,h][t][d] (natural layout)
__device__ float  g_attn[M_ * C_];               // attention out (tf32 bits)
__device__ float  g_h1[M_ * C_];                 // raw f32
__device__ float  g_x1[M_ * C_];                 // LN1 out raw f32
__device__ float  g_x1t[M_ * C_];                // LN1 out tf32 bits
__device__ float  g_ff[M_ * FF_];                // relu(x1 W1 + b1) tf32 bits
__device__ float  g_h2[M_ * C_];                 // raw f32

// ---------------- helpers ----------------
__device__ __forceinline__ uint32_t f2tf32(float f) {
    uint32_t r;
    asm("cvt.rna.tf32.f32 %0, %1;" : "=r"(r) : "f"(f));
    return r;
}
__device__ __forceinline__ float fexp2(float x) {
    float y;
    asm("ex2.approx.ftz.f32 %0, %1;" : "=f"(y) : "f"(x));
    return y;
}
__device__ __forceinline__ uint32_t pack_half2(float lo, float hi) {
    uint32_t r;
    asm("{ .reg .f16 l, h; cvt.rn.f16.f32 l, %1; cvt.rn.f16.f32 h, %2; mov.b32 %0, {l, h}; }"
        : "=r"(r) : "f"(lo), "f"(hi));
    return r;
}
__device__ __forceinline__ void mma_tf32(float* d, const uint32_t* a, const uint32_t* b) {
    asm volatile(
        "mma.sync.aligned.m16n8k8.row.col.f32.tf32.tf32.f32 "
        "{%0,%1,%2,%3}, {%4,%5,%6,%7}, {%8,%9}, {%0,%1,%2,%3};\n"
        : "+f"(d[0]), "+f"(d[1]), "+f"(d[2]), "+f"(d[3])
        : "r"(a[0]), "r"(a[1]), "r"(a[2]), "r"(a[3]),
          "r"(b[0]), "r"(b[1]));
}
__device__ __forceinline__ void mma_f16(float* d, const uint32_t* a, const uint32_t* b) {
    asm volatile(
        "mma.sync.aligned.m16n8k16.row.col.f32.f16.f16.f32 "
        "{%0,%1,%2,%3}, {%4,%5,%6,%7}, {%8,%9}, {%0,%1,%2,%3};\n"
        : "+f"(d[0]), "+f"(d[1]), "+f"(d[2]), "+f"(d[3])
        : "r"(a[0]), "r"(a[1]), "r"(a[2]), "r"(a[3]),
          "r"(b[0]), "r"(b[1]));
}
__device__ __forceinline__ uint32_t smem_u32(const void* p) {
    uint32_t a;
    asm("{ .reg .u64 t; cvta.to.shared.u64 t, %1; cvt.u32.u64 %0, t; }" : "=r"(a) : "l"(p));
    return a;
}
#define LDMATRIX_X4(r0, r1, r2, r3, addr) \
    asm volatile("ldmatrix.sync.aligned.m8n8.x4.shared.b16 {%0,%1,%2,%3}, [%4];" \
        : "=r"(r0), "=r"(r1), "=r"(r2), "=r"(r3) : "r"(addr))
#define LDMATRIX_X4_TRANS(r0, r1, r2, r3, addr) \
    asm volatile("ldmatrix.sync.aligned.m8n8.x4.trans.shared.b16 {%0,%1,%2,%3}, [%4];" \
        : "=r"(r0), "=r"(r1), "=r"(r2), "=r"(r3) : "r"(addr))
#define CP_ASYNC16(dst_u32, src_ptr) \
    asm volatile("cp.async.ca.shared.global [%0], [%1], 16;\n" \
        :: "r"(dst_u32), "l"(__cvta_generic_to_global(src_ptr)) : "memory")
#define CP_COMMIT() asm volatile("cp.async.commit_group;\n" ::: "memory")
#define CP_WAIT0()  asm volatile("cp.async.wait_group 0;\n" ::: "memory")
#define CP_WAIT1()  asm volatile("cp.async.wait_group 1;\n" ::: "memory")

// ---------------- tf32 convert kernel ----------------
__global__ void cvt_tf32_kernel(const float* __restrict__ in, float* __restrict__ out, int n4) {
    int i = blockIdx.x * blockDim.x + threadIdx.x;
    if (i >= n4) return;
    float4 v = ((const float4*)in)[i];
    uint4 o;
    o.x = f2tf32(v.x); o.y = f2tf32(v.y); o.z = f2tf32(v.z); o.w = f2tf32(v.w);
    ((uint4*)out)[i] = o;
}

// ---------------- weight pack (stores tf32 bits) ----------------
__global__ void pack_qkv_kernel(const float* __restrict__ Wq,
                                const float* __restrict__ Wk,
                                const float* __restrict__ Wv) {
    int idx = blockIdx.x * blockDim.x + threadIdx.x;
    if (idx >= C_ * 3 * C_) return;
    int c   = idx / (3 * C_);
    int rem = idx - c * (3 * C_);
    int s   = rem >> 10;
    int r2  = rem & 1023;
    int h   = r2 >> 6;
    int d   = r2 & 63;
    const float* W = (s == 0) ? Wq : ((s == 1) ? Wk : Wv);
    g_Wqkv[idx] = __uint_as_float(f2tf32(W[(h * C_ + c) * HD_ + d]));
}

// ============ tf32 GEMM v2: cp.async 3-stage pipeline, 2 CTAs/SM ============
constexpr int EPI_QKV       = 0;
constexpr int EPI_BIAS_RELU = 1;
constexpr int EPI_BIAS_RES  = 2;

#define BM 128
#define BN 128
#define BK 32
#define ASW 36
#define BSW 136
#define A_TILE_W (BM * ASW)
#define B_TILE_W (BK * BSW)
#define STAGE_W  (A_TILE_W + B_TILE_W)
#define GEMM_SMEM_BYTES (3 * STAGE_W * 4)

template <int EPI>
__global__ __launch_bounds__(256, 2)
void gemm_tc(const float* __restrict__ A, const float* __restrict__ Bmat,
             const float* __restrict__ bias, const float* __restrict__ res,
             float* __restrict__ Cout, int M, int N, int K) {
    extern __shared__ __align__(16) char smraw[];
    uint32_t* S32 = (uint32_t*)smraw;
    const uint32_t smb = smem_u32(smraw);

    const int tid = threadIdx.x;
    const int wid = tid >> 5;
    const int lane = tid & 31;
    const int g  = lane >> 2;
    const int tg = lane & 3;
    const int wm = (wid >> 2) * 64;
    const int wn = (wid & 3) * 32;
    const int bm = blockIdx.y * BM;
    const int bn = blockIdx.x * BN;

    float acc[4][4][4];
#pragma unroll
    for (int mi = 0; mi < 4; mi++)
#pragma unroll
        for (int ni = 0; ni < 4; ni++)
#pragma unroll
            for (int j = 0; j < 4; j++) acc[mi][ni][j] = 0.f;

    const int KT = K / BK;

    auto issue = [&](int kt) {
        if (kt < KT) {
            const int k0 = kt * BK;
            const uint32_t base = (uint32_t)((kt % 3) * STAGE_W);
#pragma unroll
            for (int i = 0; i < 4; i++) {
                int f = i * 256 + tid;
                int r = f >> 3, c = f & 7;
                CP_ASYNC16(smb + (base + r * ASW + c * 4) * 4,
                           A + (size_t)(bm + r) * K + k0 + c * 4);
            }
#pragma unroll
            for (int i = 0; i < 4; i++) {
                int f = i * 256 + tid;
                int k = f >> 5, n4 = f & 31;
                CP_ASYNC16(smb + (base + A_TILE_W + k * BSW + n4 * 4) * 4,
                           Bmat + (size_t)(k0 + k) * N + bn + n4 * 4);
            }
        }
        CP_COMMIT();
    };

    issue(0);
    issue(1);

    for (int kt = 0; kt < KT; ++kt) {
        CP_WAIT1();
        __syncthreads();
        issue(kt + 2);

        const uint32_t* Abuf = S32 + (kt % 3) * STAGE_W;
        const uint32_t* Bbuf = Abuf + A_TILE_W;

#pragma unroll
        for (int kk8 = 0; kk8 < 4; kk8++) {
            const int kk = kk8 * 8;
            uint32_t af[4][4], bf[4][2];
#pragma unroll
            for (int mi = 0; mi < 4; mi++) {
                int m0 = wm + mi * 16 + g;
                af[mi][0] = Abuf[m0 * ASW + kk + tg];
                af[mi][1] = Abuf[(m0 + 8) * ASW + kk + tg];
                af[mi][2] = Abuf[m0 * ASW + kk + tg + 4];
                af[mi][3] = Abuf[(m0 + 8) * ASW + kk + tg + 4];
            }
#pragma unroll
            for (int ni = 0; ni < 4; ni++) {
                int n0 = wn + ni * 8 + g;
                bf[ni][0] = Bbuf[(kk + tg) * BSW + n0];
                bf[ni][1] = Bbuf[(kk + tg + 4) * BSW + n0];
            }
#pragma unroll
            for (int mi = 0; mi < 4; mi++)
#pragma unroll
                for (int ni = 0; ni < 4; ni++)
                    mma_tf32(acc[mi][ni], af[mi], bf[ni]);
        }
    }

#pragma unroll
    for (int mi = 0; mi < 4; mi++) {
#pragma unroll
        for (int ni = 0; ni < 4; ni++) {
#pragma unroll
            for (int half = 0; half < 2; half++) {
                int row = bm + wm + mi * 16 + g + half * 8;
                int col = bn + wn + ni * 8 + tg * 2;
                float v0 = acc[mi][ni][half * 2 + 0];
                float v1 = acc[mi][ni][half * 2 + 1];
                if (EPI == EPI_QKV) {
                    int s  = col >> 10;
                    int h  = (col >> 6) & (H_ - 1);
                    int d0 = col & 63;
                    int bb = row >> 11;
                    int t  = row & 2047;
                    size_t off = (((size_t)(bb * H_ + h) * T_) + t) * HD_ + d0;
                    if (s == 0) {
                        // fold softmax scale AND log2(e) into Q
                        const float qs = 0.125f * 1.44269504f;
                        *(__half2*)(g_qh + off) = __floats2half2_rn(v0 * qs, v1 * qs);
                    } else if (s == 1) {
                        *(__half2*)(g_kh + off) = __floats2half2_rn(v0, v1);
                    } else {
                        *(__half2*)(g_vh + off) = __floats2half2_rn(v0, v1);
                    }
                } else if (EPI == EPI_BIAS_RELU) {
                    float2 bv = *(const float2*)(bias + col);
                    float2 o;
                    o.x = __uint_as_float(f2tf32(fmaxf(v0 + bv.x, 0.f)));
                    o.y = __uint_as_float(f2tf32(fmaxf(v1 + bv.y, 0.f)));
                    *(float2*)(Cout + (size_t)row * N + col) = o;
                } else {
                    float2 bv = *(const float2*)(bias + col);
                    float2 rv = *(const float2*)(res + (size_t)row * N + col);
                    float2 o = make_float2(v0 + bv.x + rv.x, v1 + bv.y + rv.y);
                    *(float2*)(Cout + (size_t)row * N + col) = o;
                }
            }
        }
    }
}

// ====== fp16 TC flash attention v2: 3-stage ring, prefetch-2, ONE sync/iter ======
// CTA: 64 q-rows, 4 warps, 4 CTAs/SM. Softmax in log2 domain (Q pre-scaled by log2e).
#define HSW 36                                   // row stride in 32-bit words
#define TILE_WORDS (64 * HSW)                    // 2304 words (one K or V tile)
#define V2_STAGE_W (2 * TILE_WORDS)              // K+V per stage: 4608 words
#define ATTN_SMEM_BYTES (3 * V2_STAGE_W * 4)     // 55296 B

__global__ __launch_bounds__(128, 4)
void attn_tc_kernel() {
    extern __shared__ __align__(16) char smraw[];
    uint32_t* S32 = (uint32_t*)smraw;
    const uint32_t smb = smem_u32(smraw);

    const int tid  = threadIdx.x;
    const int wid  = tid >> 5;                   // 0..3
    const int lane = tid & 31;
    const int g    = lane >> 2;
    const int tg   = lane & 3;
    const int bh   = blockIdx.y;
    const int qi   = gridDim.x - 1 - blockIdx.x; // heavy tiles first
    const int qr0  = qi * 64;

    const __half* qb = g_qh + (size_t)bh * T_ * HD_;
    const __half* kb = g_kh + (size_t)bh * T_ * HD_;
    const __half* vb = g_vh + (size_t)bh * T_ * HD_;

    // ---- stage Q (64 rows) through stage-2 region, extract frags, free it ----
    uint32_t* Qstage = S32 + 2 * V2_STAGE_W;
    for (int j = tid; j < 512; j += 128) {       // 64 rows x 8 uint4-of-halfs
        int r  = j >> 3;
        int c8 = j & 7;
        uint4 v = *(const uint4*)(qb + (size_t)(qr0 + r) * HD_ + c8 * 8);
        *(uint4*)(Qstage + r * HSW + c8 * 4) = v;
    }
    __syncthreads();
    const int mrow = wid * 16;
    uint32_t qf[4][4];
#pragma unroll
    for (int c = 0; c < 4; c++) {
        qf[c][0] = Qstage[(mrow + g) * HSW + c * 8 + tg];
        qf[c][1] = Qstage[(mrow + 8 + g) * HSW + c * 8 + tg];
        qf[c][2] = Qstage[(mrow + g) * HSW + c * 8 + tg + 4];
        qf[c][3] = Qstage[(mrow + 8 + g) * HSW + c * 8 + tg + 4];
    }
    __syncthreads();                             // stage-2 region now free

    // per-lane ldmatrix offsets
    const int tsel = lane >> 3;
    const int rowi = lane & 7;
    const uint32_t klm =
        (uint32_t)(((tsel & 2) ? 8 : 0) + rowi) * HSW + (uint32_t)((tsel & 1) * 4);
    const uint32_t vlm =
        (uint32_t)(((tsel & 1) ? 8 : 0) + rowi) * HSW + (uint32_t)((tsel >> 1) * 4);

    float m_s[2] = {-1e30f, -1e30f};             // log2-domain running max
    float l_s[2] = {0.f, 0.f};
    float oacc[8][4];
#pragma unroll
    for (int ni = 0; ni < 8; ni++)
#pragma unroll
        for (int j = 0; j < 4; j++) oacc[ni][j] = 0.f;

    const int nblocks = qi + 1;                  // keys 0 .. 64*qi+63

    auto issue = [&](int ib) {
        if (ib < nblocks) {
            const int st  = ib % 3;
            const int kc0 = ib * 64;
            const uint32_t kw = (uint32_t)(st * V2_STAGE_W);
            const uint32_t vw = kw + TILE_WORDS;
#pragma unroll
            for (int t = 0; t < 4; t++) {
                int j   = tid + t * 128;         // 0..511
                int row = j >> 3;
                int c8  = j & 7;
                CP_ASYNC16(smb + (kw + row * HSW + c8 * 4) * 4,
                           kb + (size_t)(kc0 + row) * HD_ + c8 * 8);
                CP_ASYNC16(smb + (vw + row * HSW + c8 * 4) * 4,
                           vb + (size_t)(kc0 + row) * HD_ + c8 * 8);
            }
        }
        CP_COMMIT();
    };

    issue(0);
    issue(1);

    for (int ib = 0; ib < nblocks; ib++) {
        const int kc0 = ib * 64;
        const int st  = ib % 3;
        const uint32_t kbase = smb + ((uint32_t)(st * V2_STAGE_W) + klm) * 4;
        const uint32_t vbase = smb + ((uint32_t)(st * V2_STAGE_W + TILE_WORDS) + vlm) * 4;

        CP_WAIT1();          // tile ib complete (<=1 group outstanding)
        __syncthreads();     // publish tile ib; all warps done with tile ib-1
        issue(ib + 2);       // overwrites stage (ib-1)%3 — safe after the sync

        // ---- S = Q K^T (log2-scaled) ----
        float sacc[8][4];
#pragma unroll
        for (int ni = 0; ni < 8; ni++)
#pragma unroll
            for (int j = 0; j < 4; j++) sacc[ni][j] = 0.f;
#pragma unroll
        for (int c = 0; c < 4; c++) {
#pragma unroll
            for (int p = 0; p < 4; p++) {
                uint32_t b0, b1, b2, b3;
                LDMATRIX_X4(b0, b1, b2, b3,
                            kbase + (uint32_t)(p * 16 * HSW + c * 8) * 4);
                uint32_t bf0[2] = {b0, b1};
                uint32_t bf1[2] = {b2, b3};
                mma_f16(sacc[2 * p],     qf[c], bf0);
                mma_f16(sacc[2 * p + 1], qf[c], bf1);
            }
        }

        // ---- causal mask (near diagonal only) ----
        if (kc0 + 63 > qr0 + mrow) {
#pragma unroll
            for (int ni = 0; ni < 8; ni++) {
#pragma unroll
                for (int j = 0; j < 4; j++) {
                    int row = qr0 + mrow + g + ((j >= 2) ? 8 : 0);
                    int col = kc0 + ni * 8 + tg * 2 + (j & 1);
                    if (col > row) sacc[ni][j] = -1e30f;
                }
            }
        }

        // ---- online softmax (log2 domain, ex2); packed P reuses dead sacc slots ----
#pragma unroll
        for (int r = 0; r < 2; r++) {
            float mx0 = fmaxf(fmaxf(sacc[0][r*2], sacc[0][r*2+1]),
                              fmaxf(sacc[1][r*2], sacc[1][r*2+1]));
            float mx1 = fmaxf(fmaxf(sacc[2][r*2], sacc[2][r*2+1]),
                              fmaxf(sacc[3][r*2], sacc[3][r*2+1]));
            float mx2 = fmaxf(fmaxf(sacc[4][r*2], sacc[4][r*2+1]),
                              fmaxf(sacc[5][r*2], sacc[5][r*2+1]));
            float mx3 = fmaxf(fmaxf(sacc[6][r*2], sacc[6][r*2+1]),
                              fmaxf(sacc[7][r*2], sacc[7][r*2+1]));
            float mx = fmaxf(fmaxf(mx0, mx1), fmaxf(mx2, mx3));
            mx = fmaxf(mx, m_s[r]);
            mx = fmaxf(mx, __shfl_xor_sync(0xFFFFFFFFu, mx, 1));
            mx = fmaxf(mx, __shfl_xor_sync(0xFFFFFFFFu, mx, 2));
            float alpha = fexp2(m_s[r] - mx);
            m_s[r] = mx;
            float sum = 0.f;
#pragma unroll
            for (int ni = 0; ni < 8; ni++) {
                float p0 = fexp2(sacc[ni][r * 2]     - mx);
                float p1 = fexp2(sacc[ni][r * 2 + 1] - mx);
                sum += p0 + p1;
                sacc[ni][r * 2] = __uint_as_float(pack_half2(p0, p1));
            }
            sum += __shfl_xor_sync(0xFFFFFFFFu, sum, 1);
            sum += __shfl_xor_sync(0xFFFFFFFFu, sum, 2);
            l_s[r] = l_s[r] * alpha + sum;
#pragma unroll
            for (int ni = 0; ni < 8; ni++) {
                oacc[ni][r * 2]     *= alpha;
                oacc[ni][r * 2 + 1] *= alpha;
            }
        }

        // ---- O += P V : A-frags from packed sacc slots, V via ldmatrix.trans ----
#pragma unroll
        for (int c = 0; c < 4; c++) {
            uint32_t af[4] = {__float_as_uint(sacc[2 * c][0]),
                              __float_as_uint(sacc[2 * c][2]),
                              __float_as_uint(sacc[2 * c + 1][0]),
                              __float_as_uint(sacc[2 * c + 1][2])};
#pragma unroll
            for (int p = 0; p < 4; p++) {
                uint32_t b0, b1, b2, b3;
                LDMATRIX_X4_TRANS(b0, b1, b2, b3,
                                  vbase + (uint32_t)(c * 16 * HSW + p * 8) * 4);
                uint32_t bf0[2] = {b0, b1};
                uint32_t bf1[2] = {b2, b3};
                mma_f16(oacc[2 * p],     af, bf0);
                mma_f16(oacc[2 * p + 1], af, bf1);
            }
        }
        // no trailing sync: next iteration's sync (after WAIT) provides it
    }

    // ---- epilogue: normalize, store concat layout as tf32 bits ----
    const int b = bh >> 4;
    const int h = bh & 15;
#pragma unroll
    for (int r = 0; r < 2; r++) {
        float inv = 1.f / l_s[r];
        int t = qr0 + mrow + g + r * 8;
        float* dst = g_attn + ((size_t)(b * T_ + t)) * C_ + h * HD_;
#pragma unroll
        for (int ni = 0; ni < 8; ni++) {
            float2 o;
            o.x = __uint_as_float(f2tf32(oacc[ni][r * 2]     * inv));
            o.y = __uint_as_float(f2tf32(oacc[ni][r * 2 + 1] * inv));
            *(float2*)(dst + ni * 8 + tg * 2) = o;
        }
    }
}

// ---------------- LayerNorm; optional tf32-bits twin output ----------------
__global__ __launch_bounds__(256)
void ln_kernel(const float* __restrict__ x, const float* __restrict__ g,
               const float* __restrict__ beta, float* __restrict__ y,
               float* __restrict__ y_t) {
    const int row = blockIdx.x;
    const int tid = threadIdx.x;
    const float* xr = x + (size_t)row * C_;

    float4 v = *(const float4*)(xr + tid * 4);
    float s  = v.x + v.y + v.z + v.w;
    float s2 = v.x * v.x + v.y * v.y + v.z * v.z + v.w * v.w;
#pragma unroll
    for (int o = 16; o > 0; o >>= 1) {
        s  += __shfl_xor_sync(0xFFFFFFFFu, s, o);
        s2 += __shfl_xor_sync(0xFFFFFFFFu, s2, o);
    }
    __shared__ float sh[16];
    __shared__ float mean_sh, istd_sh;
    int w = tid >> 5, l = tid & 31;
    if (l == 0) { sh[w] = s; sh[w + 8] = s2; }
    __syncthreads();
    if (tid == 0) {
        float ts = 0.f, ts2 = 0.f;
#pragma unroll
        for (int i = 0; i < 8; i++) { ts += sh[i]; ts2 += sh[i + 8]; }
        float mean = ts * (1.f / C_);
        float var  = ts2 * (1.f / C_) - mean * mean;
        mean_sh = mean;
        istd_sh = rsqrtf(var + 1e-5f);
    }
    __syncthreads();
    float mean = mean_sh, istd = istd_sh;
    float4 gv = *(const float4*)(g + tid * 4);
    float4 bv = *(const float4*)(beta + tid * 4);
    float4 out;
    out.x = (v.x - mean) * istd * gv.x + bv.x;
    out.y = (v.y - mean) * istd * gv.y + bv.y;
    out.z = (v.z - mean) * istd * gv.z + bv.z;
    out.w = (v.w - mean) * istd * gv.w + bv.w;
    *(float4*)(y + (size_t)row * C_ + tid * 4) = out;
    if (y_t) {
        uint4 ot;
        ot.x = f2tf32(out.x); ot.y = f2tf32(out.y);
        ot.z = f2tf32(out.z); ot.w = f2tf32(out.w);
        *(uint4*)(y_t + (size_t)row * C_ + tid * 4) = ot;
    }
}

// ---------------- launch ----------------
extern "C" void kernel_launch(void* const* d_in, const int* in_sizes, int n_in,
                              void* d_out, int out_size) {
    (void)in_sizes; (void)n_in; (void)out_size;
    const float* x   = (const float*)d_in[0];
    const float* Wq  = (const float*)d_in[1];
    const float* Wk  = (const float*)d_in[2];
    const float* Wv  = (const float*)d_in[3];
    const float* Wp  = (const float*)d_in[4];
    const float* bp  = (const float*)d_in[5];
    const float* W1  = (const float*)d_in[6];
    const float* b1  = (const float*)d_in[7];
    const float* W2  = (const float*)d_in[8];
    const float* b2  = (const float*)d_in[9];
    const float* g1  = (const float*)d_in[10];
    const float* be1 = (const float*)d_in[11];
    const float* g2  = (const float*)d_in[12];
    const float* be2 = (const float*)d_in[13];

    void *p_xt_, *p_Wpt_, *p_W1t_, *p_W2t_, *p_wqkv_, *p_attn_, *p_h1_, *p_x1_, *p_x1t_, *p_ff_, *p_h2_;
    cudaGetSymbolAddress(&p_xt_,   g_xt);
    cudaGetSymbolAddress(&p_Wpt_,  g_Wpt);
    cudaGetSymbolAddress(&p_W1t_,  g_W1t);
    cudaGetSymbolAddress(&p_W2t_,  g_W2t);
    cudaGetSymbolAddress(&p_wqkv_, g_Wqkv);
    cudaGetSymbolAddress(&p_attn_, g_attn);
    cudaGetSymbolAddress(&p_h1_,   g_h1);
    cudaGetSymbolAddress(&p_x1_,   g_x1);
    cudaGetSymbolAddress(&p_x1t_,  g_x1t);
    cudaGetSymbolAddress(&p_ff_,   g_ff);
    cudaGetSymbolAddress(&p_h2_,   g_h2);
    float* p_xt   = (float*)p_xt_;
    float* p_Wpt  = (float*)p_Wpt_;
    float* p_W1t  = (float*)p_W1t_;
    float* p_W2t  = (float*)p_W2t_;
    float* p_wqkv = (float*)p_wqkv_;
    float* p_attn = (float*)p_attn_;
    float* p_h1   = (float*)p_h1_;
    float* p_x1   = (float*)p_x1_;
    float* p_x1t  = (float*)p_x1t_;
    float* p_ff   = (float*)p_ff_;
    float* p_h2   = (float*)p_h2_;

    cudaFuncSetAttribute(attn_tc_kernel,
                         cudaFuncAttributeMaxDynamicSharedMemorySize, ATTN_SMEM_BYTES);
    cudaFuncSetAttribute(gemm_tc<EPI_QKV>,
                         cudaFuncAttributeMaxDynamicSharedMemorySize, GEMM_SMEM_BYTES);
    cudaFuncSetAttribute(gemm_tc<EPI_BIAS_RELU>,
                         cudaFuncAttributeMaxDynamicSharedMemorySize, GEMM_SMEM_BYTES);
    cudaFuncSetAttribute(gemm_tc<EPI_BIAS_RES>,
                         cudaFuncAttributeMaxDynamicSharedMemorySize, GEMM_SMEM_BYTES);

    // 0. tf32 pre-conversions (x, Wp, W1, W2)
    cvt_tf32_kernel<<<(M_ * C_ / 4 + 255) / 256, 256>>>(x,  p_xt,  M_ * C_ / 4);
    cvt_tf32_kernel<<<(C_ * C_ / 4 + 255) / 256, 256>>>(Wp, p_Wpt, C_ * C_ / 4);
    cvt_tf32_kernel<<<(C_ * FF_ / 4 + 255) / 256, 256>>>(W1, p_W1t, C_ * FF_ / 4);
    cvt_tf32_kernel<<<(FF_ * C_ / 4 + 255) / 256, 256>>>(W2, p_W2t, FF_ * C_ / 4);
    // 1. pack qkv weights -> [C, 3C] tf32 bits
    pack_qkv_kernel<<<(C_ * 3 * C_ + 255) / 256, 256>>>(Wq, Wk, Wv);
    // 2. QKV projection, epilogue converts to fp16 (Q scaled by 0.125*log2e)
    gemm_tc<EPI_QKV><<<dim3(3 * C_ / BN, M_ / BM), 256, GEMM_SMEM_BYTES>>>(
        p_xt, p_wqkv, nullptr, nullptr, nullptr, M_, 3 * C_, C_);
    // 3. causal attention v2 (3-stage ring, 1 sync/iter) -> tf32-bit concat output
    attn_tc_kernel<<<dim3(T_ / 64, B_ * H_), 128, ATTN_SMEM_BYTES>>>();
    // 4. out proj + bias + residual
    gemm_tc<EPI_BIAS_RES><<<dim3(C_ / BN, M_ / BM), 256, GEMM_SMEM_BYTES>>>(
        p_attn, p_Wpt, bp, x, p_h1, M_, C_, C_);
    // 5. LN1 (raw + tf32 twin)
    ln_kernel<<<M_, 256>>>(p_h1, g1, be1, p_x1, p_x1t);
    // 6. FFN up + relu (tf32-bit out)
    gemm_tc<EPI_BIAS_RELU><<<dim3(FF_ / BN, M_ / BM), 256, GEMM_SMEM_BYTES>>>(
        p_x1t, p_W1t, b1, nullptr, p_ff, M_, FF_, C_);
    // 7. FFN down + bias + residual
    gemm_tc<EPI_BIAS_RES><<<dim3(C_ / BN, M_ / BM), 256, GEMM_SMEM_BYTES>>>(
        p_ff, p_W2t, b2, p_x1, p_h2, M_, C_, FF_);
    // 8. LN2 -> d_out
    ln_kernel<<<M_, 256>>>(p_h2, g2, be2, (float*)d_out, nullptr);
}